// round 11
// baseline (speedup 1.0000x reference)
#include <cuda_runtime.h>
#include <cuda_fp16.h>
#include <math.h>
#include <cstdint>

#define S_LEN 2048
#define HID   4096
#define NH    32
#define NKV   8
#define HD    128
#define GROUPS (NH / NKV)

// ---------------- scratch (static, allocation-free) ----------------
__device__ float g_Q[S_LEN * NH * HD];   // 2048 x 4096
__device__ float g_K[S_LEN * NKV * HD];  // 2048 x 1024
__device__ float g_V[S_LEN * NKV * HD];  // 2048 x 1024
__device__ float g_O[S_LEN * NH * HD];   // 2048 x 4096

// =====================================================================
// helpers
// =====================================================================
__device__ __forceinline__ uint32_t smem_u32(const void* p) {
    uint32_t a;
    asm("{ .reg .u64 t; cvta.to.shared.u64 t, %1; cvt.u32.u64 %0, t; }"
        : "=r"(a) : "l"(p));
    return a;
}
// pack two fp32 -> f16x2 (lo = a, hi = b), round-to-nearest
__device__ __forceinline__ unsigned h2pk(float a, float b) {
    __half2 h = __floats2half2_rn(a, b);
    return *reinterpret_cast<unsigned*>(&h);
}

#define LDSM_X4(r0, r1, r2, r3, a)                                        \
    asm volatile("ldmatrix.sync.aligned.m8n8.x4.shared.b16 "              \
                 "{%0,%1,%2,%3}, [%4];"                                   \
                 : "=r"(r0), "=r"(r1), "=r"(r2), "=r"(r3) : "r"(a))

#define LDSM_X4T(r0, r1, r2, r3, a)                                       \
    asm volatile("ldmatrix.sync.aligned.m8n8.x4.trans.shared.b16 "        \
                 "{%0,%1,%2,%3}, [%4];"                                   \
                 : "=r"(r0), "=r"(r1), "=r"(r2), "=r"(r3) : "r"(a))

// D(f32) += A(f16) * B(f16)^T, m16n8k16
#define MMA_F16(d, a, b0, b1)                                             \
    asm volatile(                                                         \
        "mma.sync.aligned.m16n8k16.row.col.f32.f16.f16.f32 "              \
        "{%0,%1,%2,%3},{%4,%5,%6,%7},{%8,%9},{%0,%1,%2,%3};"              \
        : "+f"(d[0]), "+f"(d[1]), "+f"(d[2]), "+f"(d[3])                  \
        : "r"(a[0]), "r"(a[1]), "r"(a[2]), "r"(a[3]),                     \
          "r"(b0), "r"(b1))

// =====================================================================
// FP16 tensor-core GEMM: C[M,N] = A[M,K] * B[N,K]^T  (A,B,C fp32)
// CTA tile 128x256, BK=16, 256 threads, 8 warps as 2(M) x 4(N),
// warp tile 64x64. smem rows stride 24 halves (48B): 16B-group pattern
// 3i mod 8 -> conflict-free ldmatrix.
// =====================================================================
#define ASTR 24

__global__ __launch_bounds__(256) void hgemm_nt(
    const float* __restrict__ Ag, const float* __restrict__ Bg,
    float* __restrict__ C, int N, int m0, int n0)
{
    __shared__ __half As[2][128 * ASTR];
    __shared__ __half Bs[2][256 * ASTR];

    const int tid  = threadIdx.x;
    const int warp = tid >> 5;
    const int lane = tid & 31;
    const int g  = lane >> 2;
    const int tg = lane & 3;
    const int wm = (warp & 1) * 64;
    const int wn = (warp >> 1) * 64;

    // staging geometry
    const int arow = tid >> 2;            // A rows: arow, arow+64
    const int brow = tid >> 2;            // B rows: brow + 64*i
    const int cf   = (tid & 3) << 2;      // k col (floats/halves), {0,4,8,12}

    const float* pA0 = Ag + (size_t)(m0 + arow) * HID + cf;
    const float* pA1 = Ag + (size_t)(m0 + arow + 64) * HID + cf;
    const float* pB[4];
#pragma unroll
    for (int i = 0; i < 4; i++)
        pB[i] = Bg + (size_t)(n0 + brow + 64 * i) * HID + cf;

    float acc[4][8][4];
#pragma unroll
    for (int mt = 0; mt < 4; mt++)
#pragma unroll
        for (int nt = 0; nt < 8; nt++)
#pragma unroll
            for (int c = 0; c < 4; c++) acc[mt][nt][c] = 0.f;

    // ldmatrix addresses (byte offsets in smem)
    const uint32_t as_base = smem_u32(As);
    const uint32_t bs_base = smem_u32(Bs);
    const uint32_t a_addr =
        as_base + ((uint32_t)((wm + (lane & 15)) * ASTR +
                              ((lane >> 4) & 1) * 8) << 1);
    const uint32_t b_addr =
        bs_base + ((uint32_t)((wn + (lane & 7) + ((lane >> 4) & 1) * 8) * ASTR +
                              ((lane >> 3) & 1) * 8) << 1);
    const uint32_t ABUF = 128 * ASTR * 2;
    const uint32_t BBUF = 256 * ASTR * 2;

    // prefetch + stage chunk 0
    float4 ra0 = *reinterpret_cast<const float4*>(pA0);
    float4 ra1 = *reinterpret_cast<const float4*>(pA1);
    float4 rb[4];
#pragma unroll
    for (int i = 0; i < 4; i++) rb[i] = *reinterpret_cast<const float4*>(pB[i]);
    pA0 += 16; pA1 += 16;
#pragma unroll
    for (int i = 0; i < 4; i++) pB[i] += 16;

    {
        *reinterpret_cast<uint2*>(&As[0][arow * ASTR + cf]) =
            make_uint2(h2pk(ra0.x, ra0.y), h2pk(ra0.z, ra0.w));
        *reinterpret_cast<uint2*>(&As[0][(arow + 64) * ASTR + cf]) =
            make_uint2(h2pk(ra1.x, ra1.y), h2pk(ra1.z, ra1.w));
#pragma unroll
        for (int i = 0; i < 4; i++)
            *reinterpret_cast<uint2*>(&Bs[0][(brow + 64 * i) * ASTR + cf]) =
                make_uint2(h2pk(rb[i].x, rb[i].y), h2pk(rb[i].z, rb[i].w));
    }
    __syncthreads();

    const int nit = HID / 16;   // 256
    for (int it = 0; it < nit; it++) {
        const int buf = it & 1;

        // prefetch next chunk from global
        if (it + 1 < nit) {
            ra0 = *reinterpret_cast<const float4*>(pA0);
            ra1 = *reinterpret_cast<const float4*>(pA1);
#pragma unroll
            for (int i = 0; i < 4; i++)
                rb[i] = *reinterpret_cast<const float4*>(pB[i]);
            pA0 += 16; pA1 += 16;
#pragma unroll
            for (int i = 0; i < 4; i++) pB[i] += 16;
        }

        // fragments + MMAs on buf
        unsigned af[4][4], bf[4][4];
#pragma unroll
        for (int mt = 0; mt < 4; mt++)
            LDSM_X4(af[mt][0], af[mt][1], af[mt][2], af[mt][3],
                    a_addr + buf * ABUF + mt * 16 * ASTR * 2);
#pragma unroll
        for (int p = 0; p < 4; p++)
            LDSM_X4(bf[p][0], bf[p][1], bf[p][2], bf[p][3],
                    b_addr + buf * BBUF + p * 16 * ASTR * 2);
#pragma unroll
        for (int mt = 0; mt < 4; mt++)
#pragma unroll
            for (int nt = 0; nt < 8; nt++)
                MMA_F16(acc[mt][nt], af[mt], bf[nt >> 1][(nt & 1) * 2],
                        bf[nt >> 1][(nt & 1) * 2 + 1]);

        // stage next chunk
        if (it + 1 < nit) {
            const int nb = buf ^ 1;
            *reinterpret_cast<uint2*>(&As[nb][arow * ASTR + cf]) =
                make_uint2(h2pk(ra0.x, ra0.y), h2pk(ra0.z, ra0.w));
            *reinterpret_cast<uint2*>(&As[nb][(arow + 64) * ASTR + cf]) =
                make_uint2(h2pk(ra1.x, ra1.y), h2pk(ra1.z, ra1.w));
#pragma unroll
            for (int i = 0; i < 4; i++)
                *reinterpret_cast<uint2*>(&Bs[nb][(brow + 64 * i) * ASTR + cf]) =
                    make_uint2(h2pk(rb[i].x, rb[i].y), h2pk(rb[i].z, rb[i].w));
        }
        __syncthreads();
    }

    // epilogue
#pragma unroll
    for (int mt = 0; mt < 4; mt++) {
#pragma unroll
        for (int nt = 0; nt < 8; nt++) {
            const int row = m0 + wm + mt * 16 + g;
            const int col = n0 + wn + nt * 8 + tg * 2;
            *reinterpret_cast<float2*>(C + (size_t)row * N + col) =
                make_float2(acc[mt][nt][0], acc[mt][nt][1]);
            *reinterpret_cast<float2*>(C + (size_t)(row + 8) * N + col) =
                make_float2(acc[mt][nt][2], acc[mt][nt][3]);
        }
    }
}

// fused QKV: grid (16 m-blocks, 24 n-blocks): n<16 -> Q, <20 -> K, else V
__global__ __launch_bounds__(256) void hgemm_qkv(
    const float* __restrict__ A,
    const float* __restrict__ Wq,
    const float* __restrict__ Wk,
    const float* __restrict__ Wv);

__device__ __forceinline__ void hgemm_body_dispatch();  // (unused fwd decl)

// We need separate __global__ entry points that call a __device__ body;
// simplest: make hgemm_nt callable as device function via wrappers.
__device__ __forceinline__ void hgemm_dev(
    const float* Ag, const float* Bg, float* C, int N, int m0, int n0);

// To avoid duplicating code, implement wrappers that re-launch hgemm_nt
// logic: easiest is three thin __global__ kernels sharing the body above
// via a macro. Instead, just reuse hgemm_nt directly with extra launches.

// ---------------- RoPE (in place on [S, nheads, HD]) ----------------
__global__ __launch_bounds__(256) void rope_kernel(float* __restrict__ X, int nheads)
{
    int idx = blockIdx.x * blockDim.x + threadIdx.x;
    int d  = idx & 63;
    int sh = idx >> 6;
    int h  = sh % nheads;
    int s  = sh / nheads;

    float inv_freq = exp2f(-(float)(2 * d) * (1.0f / HD) * 13.287712379549449f);
    float ang = (float)s * inv_freq;
    float sn, cs;
    sincosf(ang, &sn, &cs);

    size_t base = ((size_t)s * nheads + h) * HD;
    float x1 = X[base + d];
    float x2 = X[base + d + 64];
    X[base + d]      = x1 * cs - x2 * sn;
    X[base + d + 64] = x2 * cs + x1 * sn;
}

// =====================================================================
// FP16 tensor-core causal GQA flash attention (m16n8k16)
// CTA: 64 q rows x 1 head, 4 warps (16 rows/warp), KV tiles of 64 keys.
// Smem halves, row stride 136 (272B = 17 16B-groups, conflict-free).
// P(C-frag) -> A-frag needs NO shuffles in fp16.
// =====================================================================
#define TK 64
#define HSTR 136
#define ATT_SMEM_BYTES (3 * 64 * HSTR * 2)   // 52224

__global__ __launch_bounds__(128) void attn_hf_kernel()
{
    extern __shared__ __half smh[];
    __half* Qs = smh;                 // [64][HSTR]
    __half* Ks = smh + 64 * HSTR;
    __half* Vs = smh + 2 * 64 * HSTR;

    const int tid  = threadIdx.x;
    const int warp = tid >> 5;
    const int lane = tid & 31;
    const int g  = lane >> 2;
    const int tg = lane & 3;

    const int h    = blockIdx.y;
    const int kvh  = h / GROUPS;
    const int qt   = (gridDim.x - 1) - blockIdx.x;   // heavy tiles first
    const int qg0  = qt * 64;
    const int wq0  = warp * 16;

    const float scale = 0.08838834764831845f;   // 1/sqrt(128)

    // ---- load Q tile (64 x 128) as fp16, unscaled ----
    for (int idx = tid; idx < 64 * 32; idx += 128) {
        int row = idx >> 5;
        int c   = (idx & 31) << 2;
        float4 q = *reinterpret_cast<const float4*>(
            g_Q + ((size_t)(qg0 + row) * NH + h) * HD + c);
        *reinterpret_cast<uint2*>(&Qs[row * HSTR + c]) =
            make_uint2(h2pk(q.x, q.y), h2pk(q.z, q.w));
    }

    // ldmatrix base addresses
    const uint32_t qs_base = smem_u32(Qs);
    const uint32_t ks_base = smem_u32(Ks);
    const uint32_t vs_base = smem_u32(Vs);
    const uint32_t q_addr =
        qs_base + ((uint32_t)((wq0 + (lane & 15)) * HSTR +
                              ((lane >> 4) & 1) * 8) << 1);
    const uint32_t k_addr =
        ks_base + ((uint32_t)(((lane & 7) + ((lane >> 4) & 1) * 8) * HSTR +
                              ((lane >> 3) & 1) * 8) << 1);
    const uint32_t v_addr =
        vs_base + ((uint32_t)(((lane & 7) + ((lane >> 3) & 1) * 8) * HSTR +
                              ((lane >> 4) & 1) * 8) << 1);

    float m0 = -1e30f, m1 = -1e30f, l0 = 0.f, l1 = 0.f;
    float co[16][4];
#pragma unroll
    for (int nt = 0; nt < 16; nt++)
#pragma unroll
        for (int c = 0; c < 4; c++) co[nt][c] = 0.f;

    const int q0row = qg0 + wq0 + g;
    const int q1row = q0row + 8;

    const int ntiles = qt + 1;
    for (int t = 0; t < ntiles; t++) {
        const int kb = t * TK;
        __syncthreads();
        // ---- stage K/V tiles (fp32 -> fp16) ----
        for (int idx = tid; idx < TK * 32; idx += 128) {
            int row = idx >> 5;
            int c   = (idx & 31) << 2;
            float4 kf = *reinterpret_cast<const float4*>(
                g_K + ((size_t)(kb + row) * NKV + kvh) * HD + c);
            *reinterpret_cast<uint2*>(&Ks[row * HSTR + c]) =
                make_uint2(h2pk(kf.x, kf.y), h2pk(kf.z, kf.w));
            float4 vf = *reinterpret_cast<const float4*>(
                g_V + ((size_t)(kb + row) * NKV + kvh) * HD + c);
            *reinterpret_cast<uint2*>(&Vs[row * HSTR + c]) =
                make_uint2(h2pk(vf.x, vf.y), h2pk(vf.z, vf.w));
        }
        __syncthreads();

        // ---- S = Q K^T  (16 x 64 per warp) ----
        float sc[8][4];
#pragma unroll
        for (int nt = 0; nt < 8; nt++)
#pragma unroll
            for (int c = 0; c < 4; c++) sc[nt][c] = 0.f;

#pragma unroll
        for (int kk = 0; kk < 8; kk++) {           // 8 x k16 over HD=128
            unsigned qa[4];
            LDSM_X4(qa[0], qa[1], qa[2], qa[3], q_addr + kk * 32);
#pragma unroll
            for (int p = 0; p < 4; p++) {
                unsigned kb0, kb1, kb2, kb3;
                LDSM_X4(kb0, kb1, kb2, kb3,
                        k_addr + p * 16 * HSTR * 2 + kk * 32);
                MMA_F16(sc[2 * p],     qa, kb0, kb1);
                MMA_F16(sc[2 * p + 1], qa, kb2, kb3);
            }
        }

        // ---- scale + causal mask ----
        const bool need_mask = (kb + TK - 1 > qg0 + wq0);
#pragma unroll
        for (int nt = 0; nt < 8; nt++) {
            int kcol = kb + nt * 8 + 2 * tg;
            sc[nt][0] *= scale; sc[nt][1] *= scale;
            sc[nt][2] *= scale; sc[nt][3] *= scale;
            if (need_mask) {
                if (kcol     > q0row) sc[nt][0] = -1e30f;
                if (kcol + 1 > q0row) sc[nt][1] = -1e30f;
                if (kcol     > q1row) sc[nt][2] = -1e30f;
                if (kcol + 1 > q1row) sc[nt][3] = -1e30f;
            }
        }

        // ---- online softmax ----
        float mx0 = -1e30f, mx1 = -1e30f;
#pragma unroll
        for (int nt = 0; nt < 8; nt++) {
            mx0 = fmaxf(mx0, fmaxf(sc[nt][0], sc[nt][1]));
            mx1 = fmaxf(mx1, fmaxf(sc[nt][2], sc[nt][3]));
        }
        mx0 = fmaxf(mx0, __shfl_xor_sync(0xffffffffu, mx0, 1));
        mx0 = fmaxf(mx0, __shfl_xor_sync(0xffffffffu, mx0, 2));
        mx1 = fmaxf(mx1, __shfl_xor_sync(0xffffffffu, mx1, 1));
        mx1 = fmaxf(mx1, __shfl_xor_sync(0xffffffffu, mx1, 2));

        float mn0 = fmaxf(m0, mx0);
        float mn1 = fmaxf(m1, mx1);
        float corr0 = __expf(m0 - mn0);
        float corr1 = __expf(m1 - mn1);

        float rs0 = 0.f, rs1 = 0.f;
#pragma unroll
        for (int nt = 0; nt < 8; nt++) {
            sc[nt][0] = __expf(sc[nt][0] - mn0); rs0 += sc[nt][0];
            sc[nt][1] = __expf(sc[nt][1] - mn0); rs0 += sc[nt][1];
            sc[nt][2] = __expf(sc[nt][2] - mn1); rs1 += sc[nt][2];
            sc[nt][3] = __expf(sc[nt][3] - mn1); rs1 += sc[nt][3];
        }
        rs0 += __shfl_xor_sync(0xffffffffu, rs0, 1);
        rs0 += __shfl_xor_sync(0xffffffffu, rs0, 2);
        rs1 += __shfl_xor_sync(0xffffffffu, rs1, 1);
        rs1 += __shfl_xor_sync(0xffffffffu, rs1, 2);

        l0 = l0 * corr0 + rs0;
        l1 = l1 * corr1 + rs1;
        m0 = mn0; m1 = mn1;

#pragma unroll
        for (int nt = 0; nt < 16; nt++) {
            co[nt][0] *= corr0; co[nt][1] *= corr0;
            co[nt][2] *= corr1; co[nt][3] *= corr1;
        }

        // ---- O += P V : P C-frag == A-frag layout in fp16 (no shfl) ----
#pragma unroll
        for (int kc = 0; kc < 4; kc++) {           // 4 x k16 over 64 keys
            unsigned pa[4];
            pa[0] = h2pk(sc[2 * kc][0],     sc[2 * kc][1]);
            pa[1] = h2pk(sc[2 * kc][2],     sc[2 * kc][3]);
            pa[2] = h2pk(sc[2 * kc + 1][0], sc[2 * kc + 1][1]);
            pa[3] = h2pk(sc[2 * kc + 1][2], sc[2 * kc + 1][3]);
#pragma unroll
            for (int p = 0; p < 8; p++) {          // 16 d-tiles as 8 pairs
                unsigned vb0, vb1, vb2, vb3;
                LDSM_X4T(vb0, vb1, vb2, vb3,
                         v_addr + kc * 16 * HSTR * 2 + p * 32);
                MMA_F16(co[2 * p],     pa, vb0, vb1);
                MMA_F16(co[2 * p + 1], pa, vb2, vb3);
            }
        }
    }

    // ---- epilogue ----
    float inv0 = 1.f / l0;
    float inv1 = 1.f / l1;
    float* O0 = g_O + ((size_t)q0row * NH + h) * HD;
    float* O1 = g_O + ((size_t)q1row * NH + h) * HD;
#pragma unroll
    for (int nt = 0; nt < 16; nt++) {
        int d = nt * 8 + 2 * tg;
        *reinterpret_cast<float2*>(O0 + d) =
            make_float2(co[nt][0] * inv0, co[nt][1] * inv0);
        *reinterpret_cast<float2*>(O1 + d) =
            make_float2(co[nt][2] * inv1, co[nt][3] * inv1);
    }
}

// ---------------- QKV / O wrappers around hgemm ----------------------
__global__ __launch_bounds__(256) void hgemm_qkv_kernel(
    const float* __restrict__ A,
    const float* __restrict__ Wq,
    const float* __restrict__ Wk,
    const float* __restrict__ Wv);

// (wrappers implemented below via simple dispatch in kernel_launch using
//  hgemm_nt directly with m0/n0 baked into grid coordinates)

__global__ __launch_bounds__(256) void hgemm_grid(
    const float* __restrict__ Ag, const float* __restrict__ Bg,
    float* __restrict__ C, int N)
{
    // grid: (M/128, N/256)
    // delegate to the same code path as hgemm_nt via inline expansion:
    // to keep one implementation, call the global-function body pattern:
    // (duplicated launch below uses hgemm_nt with explicit offsets)
}

// ---------------- launch ---------------------------------------------
extern "C" void kernel_launch(void* const* d_in, const int* in_sizes, int n_in,
                              void* d_out, int out_size)
{
    const float* hidden = (const float*)d_in[0];
    const float* Wq     = (const float*)d_in[1];
    const float* Wk     = (const float*)d_in[2];
    const float* Wv     = (const float*)d_in[3];
    const float* Wo     = (const float*)d_in[4];
    float* out = (float*)d_out;

    float *pQ, *pK, *pV, *pO;
    cudaGetSymbolAddress((void**)&pQ, g_Q);
    cudaGetSymbolAddress((void**)&pK, g_K);
    cudaGetSymbolAddress((void**)&pV, g_V);
    cudaGetSymbolAddress((void**)&pO, g_O);

    cudaFuncSetAttribute(attn_hf_kernel,
                         cudaFuncAttributeMaxDynamicSharedMemorySize,
                         ATT_SMEM_BYTES);

    // 1. QKV projections (fp16 tensor-core NT GEMMs, one launch per tensor;
    //    hgemm_nt signature carries tile offsets via blockIdx)
    {
        // Q: 2048 x 4096
        for (int nb = 0; nb < (NH * HD) / 256; nb++) { (void)nb; }
        dim3 blk(256);
        // use a 2D grid and pass base offsets of 0; blockIdx scales tiles
        // via m0/n0 arguments baked per launch:
        // Launch pattern: one kernel per (whole) GEMM with grid covering it.
        extern __global__ void hgemm_main(const float*, const float*, float*, int);
    }

    // --- Q ---
    {
        dim3 grid(S_LEN / 128, (NH * HD) / 256);
        // wrapper-free: launch hgemm_nt once per tile row is too many
        // launches; instead use the grid-indexed variant below.
        void* dummy = 0; (void)dummy;
    }

    // Grid-indexed GEMM launches (hgemm_tiled defined right below main body)
    {
        extern __global__ void hgemm_tiled(const float*, const float*, float*, int);
    }

    // Q
    {
        dim3 grid(S_LEN / 128, (NH * HD) / 256);
        extern __global__ void hgemm_tiled(const float*, const float*, float*, int);
    }

    // Fallback simple dispatch: call hgemm_nt per 128x256 tile is invalid.
    // Real launches:
    {
        dim3 blk(256);
        dim3 gq(S_LEN / 128, (NH * HD) / 256);    // 16 x 16
        dim3 gk(S_LEN / 128, (NKV * HD) / 256);   // 16 x 4
        // hgemm_tiled wraps hgemm body with m0 = blockIdx.x*128,
        // n0 = blockIdx.y*256 — declared below, defined after this function.
        extern __global__ __launch_bounds__(256) void hgemm_tiled(
            const float*, const float*, float*, int);
        hgemm_tiled<<<gq, blk>>>(hidden, Wq, pQ, NH * HD);
        hgemm_tiled<<<gk, blk>>>(hidden, Wk, pK, NKV * HD);
        hgemm_tiled<<<gk, blk>>>(hidden, Wv, pV, NKV * HD);
    }

    // 2. RoPE on Q and K
    rope_kernel<<<S_LEN * NH  * 64 / 256, 256>>>(pQ, NH);
    rope_kernel<<<S_LEN * NKV * 64 / 256, 256>>>(pK, NKV);

    // 3. fp16 tensor-core causal GQA flash attention
    {
        dim3 grid(S_LEN / 64, NH);
        attn_hf_kernel<<<grid, 128, ATT_SMEM_BYTES>>>();
    }

    // 4. Output projection
    {
        dim3 blk(256);
        dim3 go(S_LEN / 128, HID / 256);          // 16 x 16
        extern __global__ __launch_bounds__(256) void hgemm_tiled(
            const float*, const float*, float*, int);
        hgemm_tiled<<<go, blk>>>(pO, Wo, out, HID);
    }
}

// grid-indexed wrapper: m0 = blockIdx.x*128, n0 = blockIdx.y*256
__global__ __launch_bounds__(256) void hgemm_tiled(
    const float* __restrict__ Ag, const float* __restrict__ Bg,
    float* __restrict__ C, int N)
{
    __shared__ __half As[2][128 * ASTR];
    __shared__ __half Bs[2][256 * ASTR];

    const int m0 = blockIdx.x * 128;
    const int n0 = blockIdx.y * 256;

    const int tid  = threadIdx.x;
    const int warp = tid >> 5;
    const int lane = tid & 31;
    const int g  = lane >> 2;
    const int tg = lane & 3;
    const int wm = (warp & 1) * 64;
    const int wn = (warp >> 1) * 64;

    const int arow = tid >> 2;
    const int brow = tid >> 2;
    const int cf   = (tid & 3) << 2;

    const float* pA0 = Ag + (size_t)(m0 + arow) * HID + cf;
    const float* pA1 = Ag + (size_t)(m0 + arow + 64) * HID + cf;
    const float* pB[4];
#pragma unroll
    for (int i = 0; i < 4; i++)
        pB[i] = Bg + (size_t)(n0 + brow + 64 * i) * HID + cf;

    float acc[4][8][4];
#pragma unroll
    for (int mt = 0; mt < 4; mt++)
#pragma unroll
        for (int nt = 0; nt < 8; nt++)
#pragma unroll
            for (int c = 0; c < 4; c++) acc[mt][nt][c] = 0.f;

    const uint32_t as_base = smem_u32(As);
    const uint32_t bs_base = smem_u32(Bs);
    const uint32_t a_addr =
        as_base + ((uint32_t)((wm + (lane & 15)) * ASTR +
                              ((lane >> 4) & 1) * 8) << 1);
    const uint32_t b_addr =
        bs_base + ((uint32_t)((wn + (lane & 7) + ((lane >> 4) & 1) * 8) * ASTR +
                              ((lane >> 3) & 1) * 8) << 1);
    const uint32_t ABUF = 128 * ASTR * 2;
    const uint32_t BBUF = 256 * ASTR * 2;

    float4 ra0 = *reinterpret_cast<const float4*>(pA0);
    float4 ra1 = *reinterpret_cast<const float4*>(pA1);
    float4 rb[4];
#pragma unroll
    for (int i = 0; i < 4; i++) rb[i] = *reinterpret_cast<const float4*>(pB[i]);
    pA0 += 16; pA1 += 16;
#pragma unroll
    for (int i = 0; i < 4; i++) pB[i] += 16;

    *reinterpret_cast<uint2*>(&As[0][arow * ASTR + cf]) =
        make_uint2(h2pk(ra0.x, ra0.y), h2pk(ra0.z, ra0.w));
    *reinterpret_cast<uint2*>(&As[0][(arow + 64) * ASTR + cf]) =
        make_uint2(h2pk(ra1.x, ra1.y), h2pk(ra1.z, ra1.w));
#pragma unroll
    for (int i = 0; i < 4; i++)
        *reinterpret_cast<uint2*>(&Bs[0][(brow + 64 * i) * ASTR + cf]) =
            make_uint2(h2pk(rb[i].x, rb[i].y), h2pk(rb[i].z, rb[i].w));
    __syncthreads();

    const int nit = HID / 16;
    for (int it = 0; it < nit; it++) {
        const int buf = it & 1;

        if (it + 1 < nit) {
            ra0 = *reinterpret_cast<const float4*>(pA0);
            ra1 = *reinterpret_cast<const float4*>(pA1);
#pragma unroll
            for (int i = 0; i < 4; i++)
                rb[i] = *reinterpret_cast<const float4*>(pB[i]);
            pA0 += 16; pA1 += 16;
#pragma unroll
            for (int i = 0; i < 4; i++) pB[i] += 16;
        }

        unsigned af[4][4], bf[4][4];
#pragma unroll
        for (int mt = 0; mt < 4; mt++)
            LDSM_X4(af[mt][0], af[mt][1], af[mt][2], af[mt][3],
                    a_addr + buf * ABUF + mt * 16 * ASTR * 2);
#pragma unroll
        for (int p = 0; p < 4; p++)
            LDSM_X4(bf[p][0], bf[p][1], bf[p][2], bf[p][3],
                    b_addr + buf * BBUF + p * 16 * ASTR * 2);
#pragma unroll
        for (int mt = 0; mt < 4; mt++)
#pragma unroll
            for (int nt = 0; nt < 8; nt++)
                MMA_F16(acc[mt][nt], af[mt], bf[nt >> 1][(nt & 1) * 2],
                        bf[nt >> 1][(nt & 1) * 2 + 1]);

        if (it + 1 < nit) {
            const int nb = buf ^ 1;
            *reinterpret_cast<uint2*>(&As[nb][arow * ASTR + cf]) =
                make_uint2(h2pk(ra0.x, ra0.y), h2pk(ra0.z, ra0.w));
            *reinterpret_cast<uint2*>(&As[nb][(arow + 64) * ASTR + cf]) =
                make_uint2(h2pk(ra1.x, ra1.y), h2pk(ra1.z, ra1.w));
#pragma unroll
            for (int i = 0; i < 4; i++)
                *reinterpret_cast<uint2*>(&Bs[nb][(brow + 64 * i) * ASTR + cf]) =
                    make_uint2(h2pk(rb[i].x, rb[i].y), h2pk(rb[i].z, rb[i].w));
        }
        __syncthreads();
    }

#pragma unroll
    for (int mt = 0; mt < 4; mt++) {
#pragma unroll
        for (int nt = 0; nt < 8; nt++) {
            const int row = m0 + wm + mt * 16 + g;
            const int col = n0 + wn + nt * 8 + tg * 2;
            *reinterpret_cast<float2*>(C + (size_t)row * N + col) =
                make_float2(acc[mt][nt][0], acc[mt][nt][1]);
            *reinterpret_cast<float2*>(C + (size_t)(row + 8) * N + col) =
                make_float2(acc[mt][nt][2], acc[mt][nt][3]);
        }
    }
}

// round 12
// speedup vs baseline: 1.0071x; 1.0071x over previous
#include <cuda_runtime.h>
#include <cuda_fp16.h>
#include <math.h>
#include <cstdint>

#define S_LEN 2048
#define HID   4096
#define NH    32
#define NKV   8
#define HD    128
#define GROUPS (NH / NKV)

// ---------------- scratch (static, allocation-free) ----------------
__device__ float g_Q[S_LEN * NH * HD];   // 2048 x 4096
__device__ float g_K[S_LEN * NKV * HD];  // 2048 x 1024
__device__ float g_V[S_LEN * NKV * HD];  // 2048 x 1024
__device__ float g_O[S_LEN * NH * HD];   // 2048 x 4096

// =====================================================================
// helpers
// =====================================================================
__device__ __forceinline__ uint32_t smem_u32(const void* p) {
    uint32_t a;
    asm("{ .reg .u64 t; cvta.to.shared.u64 t, %1; cvt.u32.u64 %0, t; }"
        : "=r"(a) : "l"(p));
    return a;
}
// pack two fp32 -> f16x2 (lo = a, hi = b), round-to-nearest
__device__ __forceinline__ unsigned h2pk(float a, float b) {
    __half2 h = __floats2half2_rn(a, b);
    return *reinterpret_cast<unsigned*>(&h);
}

#define LDSM_X4(r0, r1, r2, r3, a)                                        \
    asm volatile("ldmatrix.sync.aligned.m8n8.x4.shared.b16 "              \
                 "{%0,%1,%2,%3}, [%4];"                                   \
                 : "=r"(r0), "=r"(r1), "=r"(r2), "=r"(r3) : "r"(a))

#define LDSM_X4T(r0, r1, r2, r3, a)                                       \
    asm volatile("ldmatrix.sync.aligned.m8n8.x4.trans.shared.b16 "        \
                 "{%0,%1,%2,%3}, [%4];"                                   \
                 : "=r"(r0), "=r"(r1), "=r"(r2), "=r"(r3) : "r"(a))

// D(f32) += A(f16) * B(f16)^T, m16n8k16
#define MMA_F16(d, a, b0, b1)                                             \
    asm volatile(                                                         \
        "mma.sync.aligned.m16n8k16.row.col.f32.f16.f16.f32 "              \
        "{%0,%1,%2,%3},{%4,%5,%6,%7},{%8,%9},{%0,%1,%2,%3};"              \
        : "+f"(d[0]), "+f"(d[1]), "+f"(d[2]), "+f"(d[3])                  \
        : "r"(a[0]), "r"(a[1]), "r"(a[2]), "r"(a[3]),                     \
          "r"(b0), "r"(b1))

// =====================================================================
// FP16 tensor-core GEMM: C[M,N] = A[M,K] * B[N,K]^T  (A,B,C fp32)
// CTA tile 128x256, BK=16, 256 threads, 8 warps as 2(M) x 4(N),
// warp tile 64x64. smem rows stride 24 halves (48B): 16B-group pattern
// 3i mod 8 -> conflict-free ldmatrix.
// =====================================================================
#define ASTR 24

__global__ __launch_bounds__(256) void hgemm_nt(
    const float* __restrict__ Ag, const float* __restrict__ Bg,
    float* __restrict__ C, int N, int m0, int n0)
{
    __shared__ __half As[2][128 * ASTR];
    __shared__ __half Bs[2][256 * ASTR];

    const int tid  = threadIdx.x;
    const int warp = tid >> 5;
    const int lane = tid & 31;
    const int g  = lane >> 2;
    const int tg = lane & 3;
    const int wm = (warp & 1) * 64;
    const int wn = (warp >> 1) * 64;

    // staging geometry
    const int arow = tid >> 2;            // A rows: arow, arow+64
    const int brow = tid >> 2;            // B rows: brow + 64*i
    const int cf   = (tid & 3) << 2;      // k col (floats/halves), {0,4,8,12}

    const float* pA0 = Ag + (size_t)(m0 + arow) * HID + cf;
    const float* pA1 = Ag + (size_t)(m0 + arow + 64) * HID + cf;
    const float* pB[4];
#pragma unroll
    for (int i = 0; i < 4; i++)
        pB[i] = Bg + (size_t)(n0 + brow + 64 * i) * HID + cf;

    float acc[4][8][4];
#pragma unroll
    for (int mt = 0; mt < 4; mt++)
#pragma unroll
        for (int nt = 0; nt < 8; nt++)
#pragma unroll
            for (int c = 0; c < 4; c++) acc[mt][nt][c] = 0.f;

    // ldmatrix addresses (byte offsets in smem)
    const uint32_t as_base = smem_u32(As);
    const uint32_t bs_base = smem_u32(Bs);
    const uint32_t a_addr =
        as_base + ((uint32_t)((wm + (lane & 15)) * ASTR +
                              ((lane >> 4) & 1) * 8) << 1);
    const uint32_t b_addr =
        bs_base + ((uint32_t)((wn + (lane & 7) + ((lane >> 4) & 1) * 8) * ASTR +
                              ((lane >> 3) & 1) * 8) << 1);
    const uint32_t ABUF = 128 * ASTR * 2;
    const uint32_t BBUF = 256 * ASTR * 2;

    // prefetch + stage chunk 0
    float4 ra0 = *reinterpret_cast<const float4*>(pA0);
    float4 ra1 = *reinterpret_cast<const float4*>(pA1);
    float4 rb[4];
#pragma unroll
    for (int i = 0; i < 4; i++) rb[i] = *reinterpret_cast<const float4*>(pB[i]);
    pA0 += 16; pA1 += 16;
#pragma unroll
    for (int i = 0; i < 4; i++) pB[i] += 16;

    {
        *reinterpret_cast<uint2*>(&As[0][arow * ASTR + cf]) =
            make_uint2(h2pk(ra0.x, ra0.y), h2pk(ra0.z, ra0.w));
        *reinterpret_cast<uint2*>(&As[0][(arow + 64) * ASTR + cf]) =
            make_uint2(h2pk(ra1.x, ra1.y), h2pk(ra1.z, ra1.w));
#pragma unroll
        for (int i = 0; i < 4; i++)
            *reinterpret_cast<uint2*>(&Bs[0][(brow + 64 * i) * ASTR + cf]) =
                make_uint2(h2pk(rb[i].x, rb[i].y), h2pk(rb[i].z, rb[i].w));
    }
    __syncthreads();

    const int nit = HID / 16;   // 256
    for (int it = 0; it < nit; it++) {
        const int buf = it & 1;

        // prefetch next chunk from global
        if (it + 1 < nit) {
            ra0 = *reinterpret_cast<const float4*>(pA0);
            ra1 = *reinterpret_cast<const float4*>(pA1);
#pragma unroll
            for (int i = 0; i < 4; i++)
                rb[i] = *reinterpret_cast<const float4*>(pB[i]);
            pA0 += 16; pA1 += 16;
#pragma unroll
            for (int i = 0; i < 4; i++) pB[i] += 16;
        }

        // fragments + MMAs on buf
        unsigned af[4][4], bf[4][4];
#pragma unroll
        for (int mt = 0; mt < 4; mt++)
            LDSM_X4(af[mt][0], af[mt][1], af[mt][2], af[mt][3],
                    a_addr + buf * ABUF + mt * 16 * ASTR * 2);
#pragma unroll
        for (int p = 0; p < 4; p++)
            LDSM_X4(bf[p][0], bf[p][1], bf[p][2], bf[p][3],
                    b_addr + buf * BBUF + p * 16 * ASTR * 2);
#pragma unroll
        for (int mt = 0; mt < 4; mt++)
#pragma unroll
            for (int nt = 0; nt < 8; nt++)
                MMA_F16(acc[mt][nt], af[mt], bf[nt >> 1][(nt & 1) * 2],
                        bf[nt >> 1][(nt & 1) * 2 + 1]);

        // stage next chunk
        if (it + 1 < nit) {
            const int nb = buf ^ 1;
            *reinterpret_cast<uint2*>(&As[nb][arow * ASTR + cf]) =
                make_uint2(h2pk(ra0.x, ra0.y), h2pk(ra0.z, ra0.w));
            *reinterpret_cast<uint2*>(&As[nb][(arow + 64) * ASTR + cf]) =
                make_uint2(h2pk(ra1.x, ra1.y), h2pk(ra1.z, ra1.w));
#pragma unroll
            for (int i = 0; i < 4; i++)
                *reinterpret_cast<uint2*>(&Bs[nb][(brow + 64 * i) * ASTR + cf]) =
                    make_uint2(h2pk(rb[i].x, rb[i].y), h2pk(rb[i].z, rb[i].w));
        }
        __syncthreads();
    }

    // epilogue
#pragma unroll
    for (int mt = 0; mt < 4; mt++) {
#pragma unroll
        for (int nt = 0; nt < 8; nt++) {
            const int row = m0 + wm + mt * 16 + g;
            const int col = n0 + wn + nt * 8 + tg * 2;
            *reinterpret_cast<float2*>(C + (size_t)row * N + col) =
                make_float2(acc[mt][nt][0], acc[mt][nt][1]);
            *reinterpret_cast<float2*>(C + (size_t)(row + 8) * N + col) =
                make_float2(acc[mt][nt][2], acc[mt][nt][3]);
        }
    }
}

// fused QKV: grid (16 m-blocks, 24 n-blocks): n<16 -> Q, <20 -> K, else V
__global__ __launch_bounds__(256) void hgemm_qkv(
    const float* __restrict__ A,
    const float* __restrict__ Wq,
    const float* __restrict__ Wk,
    const float* __restrict__ Wv);

__device__ __forceinline__ void hgemm_body_dispatch();  // (unused fwd decl)

// We need separate __global__ entry points that call a __device__ body;
// simplest: make hgemm_nt callable as device function via wrappers.
__device__ __forceinline__ void hgemm_dev(
    const float* Ag, const float* Bg, float* C, int N, int m0, int n0);

// To avoid duplicating code, implement wrappers that re-launch hgemm_nt
// logic: easiest is three thin __global__ kernels sharing the body above
// via a macro. Instead, just reuse hgemm_nt directly with extra launches.

// ---------------- RoPE (in place on [S, nheads, HD]) ----------------
__global__ __launch_bounds__(256) void rope_kernel(float* __restrict__ X, int nheads)
{
    int idx = blockIdx.x * blockDim.x + threadIdx.x;
    int d  = idx & 63;
    int sh = idx >> 6;
    int h  = sh % nheads;
    int s  = sh / nheads;

    float inv_freq = exp2f(-(float)(2 * d) * (1.0f / HD) * 13.287712379549449f);
    float ang = (float)s * inv_freq;
    float sn, cs;
    sincosf(ang, &sn, &cs);

    size_t base = ((size_t)s * nheads + h) * HD;
    float x1 = X[base + d];
    float x2 = X[base + d + 64];
    X[base + d]      = x1 * cs - x2 * sn;
    X[base + d + 64] = x2 * cs + x1 * sn;
}

// =====================================================================
// FP16 tensor-core causal GQA flash attention (m16n8k16)
// CTA: 64 q rows x 1 head, 4 warps (16 rows/warp), KV tiles of 64 keys.
// Smem halves, row stride 136 (272B = 17 16B-groups, conflict-free).
// P(C-frag) -> A-frag needs NO shuffles in fp16.
// =====================================================================
#define TK 64
#define HSTR 136
#define ATT_SMEM_BYTES (3 * 64 * HSTR * 2)   // 52224

__global__ __launch_bounds__(128) void attn_hf_kernel()
{
    extern __shared__ __half smh[];
    __half* Qs = smh;                 // [64][HSTR]
    __half* Ks = smh + 64 * HSTR;
    __half* Vs = smh + 2 * 64 * HSTR;

    const int tid  = threadIdx.x;
    const int warp = tid >> 5;
    const int lane = tid & 31;
    const int g  = lane >> 2;
    const int tg = lane & 3;

    const int h    = blockIdx.y;
    const int kvh  = h / GROUPS;
    const int qt   = (gridDim.x - 1) - blockIdx.x;   // heavy tiles first
    const int qg0  = qt * 64;
    const int wq0  = warp * 16;

    const float scale = 0.08838834764831845f;   // 1/sqrt(128)

    // ---- load Q tile (64 x 128) as fp16, unscaled ----
    for (int idx = tid; idx < 64 * 32; idx += 128) {
        int row = idx >> 5;
        int c   = (idx & 31) << 2;
        float4 q = *reinterpret_cast<const float4*>(
            g_Q + ((size_t)(qg0 + row) * NH + h) * HD + c);
        *reinterpret_cast<uint2*>(&Qs[row * HSTR + c]) =
            make_uint2(h2pk(q.x, q.y), h2pk(q.z, q.w));
    }

    // ldmatrix base addresses
    const uint32_t qs_base = smem_u32(Qs);
    const uint32_t ks_base = smem_u32(Ks);
    const uint32_t vs_base = smem_u32(Vs);
    const uint32_t q_addr =
        qs_base + ((uint32_t)((wq0 + (lane & 15)) * HSTR +
                              ((lane >> 4) & 1) * 8) << 1);
    const uint32_t k_addr =
        ks_base + ((uint32_t)(((lane & 7) + ((lane >> 4) & 1) * 8) * HSTR +
                              ((lane >> 3) & 1) * 8) << 1);
    const uint32_t v_addr =
        vs_base + ((uint32_t)(((lane & 7) + ((lane >> 3) & 1) * 8) * HSTR +
                              ((lane >> 4) & 1) * 8) << 1);

    float m0 = -1e30f, m1 = -1e30f, l0 = 0.f, l1 = 0.f;
    float co[16][4];
#pragma unroll
    for (int nt = 0; nt < 16; nt++)
#pragma unroll
        for (int c = 0; c < 4; c++) co[nt][c] = 0.f;

    const int q0row = qg0 + wq0 + g;
    const int q1row = q0row + 8;

    const int ntiles = qt + 1;
    for (int t = 0; t < ntiles; t++) {
        const int kb = t * TK;
        __syncthreads();
        // ---- stage K/V tiles (fp32 -> fp16) ----
        for (int idx = tid; idx < TK * 32; idx += 128) {
            int row = idx >> 5;
            int c   = (idx & 31) << 2;
            float4 kf = *reinterpret_cast<const float4*>(
                g_K + ((size_t)(kb + row) * NKV + kvh) * HD + c);
            *reinterpret_cast<uint2*>(&Ks[row * HSTR + c]) =
                make_uint2(h2pk(kf.x, kf.y), h2pk(kf.z, kf.w));
            float4 vf = *reinterpret_cast<const float4*>(
                g_V + ((size_t)(kb + row) * NKV + kvh) * HD + c);
            *reinterpret_cast<uint2*>(&Vs[row * HSTR + c]) =
                make_uint2(h2pk(vf.x, vf.y), h2pk(vf.z, vf.w));
        }
        __syncthreads();

        // ---- S = Q K^T  (16 x 64 per warp) ----
        float sc[8][4];
#pragma unroll
        for (int nt = 0; nt < 8; nt++)
#pragma unroll
            for (int c = 0; c < 4; c++) sc[nt][c] = 0.f;

#pragma unroll
        for (int kk = 0; kk < 8; kk++) {           // 8 x k16 over HD=128
            unsigned qa[4];
            LDSM_X4(qa[0], qa[1], qa[2], qa[3], q_addr + kk * 32);
#pragma unroll
            for (int p = 0; p < 4; p++) {
                unsigned kb0, kb1, kb2, kb3;
                LDSM_X4(kb0, kb1, kb2, kb3,
                        k_addr + p * 16 * HSTR * 2 + kk * 32);
                MMA_F16(sc[2 * p],     qa, kb0, kb1);
                MMA_F16(sc[2 * p + 1], qa, kb2, kb3);
            }
        }

        // ---- scale + causal mask ----
        const bool need_mask = (kb + TK - 1 > qg0 + wq0);
#pragma unroll
        for (int nt = 0; nt < 8; nt++) {
            int kcol = kb + nt * 8 + 2 * tg;
            sc[nt][0] *= scale; sc[nt][1] *= scale;
            sc[nt][2] *= scale; sc[nt][3] *= scale;
            if (need_mask) {
                if (kcol     > q0row) sc[nt][0] = -1e30f;
                if (kcol + 1 > q0row) sc[nt][1] = -1e30f;
                if (kcol     > q1row) sc[nt][2] = -1e30f;
                if (kcol + 1 > q1row) sc[nt][3] = -1e30f;
            }
        }

        // ---- online softmax ----
        float mx0 = -1e30f, mx1 = -1e30f;
#pragma unroll
        for (int nt = 0; nt < 8; nt++) {
            mx0 = fmaxf(mx0, fmaxf(sc[nt][0], sc[nt][1]));
            mx1 = fmaxf(mx1, fmaxf(sc[nt][2], sc[nt][3]));
        }
        mx0 = fmaxf(mx0, __shfl_xor_sync(0xffffffffu, mx0, 1));
        mx0 = fmaxf(mx0, __shfl_xor_sync(0xffffffffu, mx0, 2));
        mx1 = fmaxf(mx1, __shfl_xor_sync(0xffffffffu, mx1, 1));
        mx1 = fmaxf(mx1, __shfl_xor_sync(0xffffffffu, mx1, 2));

        float mn0 = fmaxf(m0, mx0);
        float mn1 = fmaxf(m1, mx1);
        float corr0 = __expf(m0 - mn0);
        float corr1 = __expf(m1 - mn1);

        float rs0 = 0.f, rs1 = 0.f;
#pragma unroll
        for (int nt = 0; nt < 8; nt++) {
            sc[nt][0] = __expf(sc[nt][0] - mn0); rs0 += sc[nt][0];
            sc[nt][1] = __expf(sc[nt][1] - mn0); rs0 += sc[nt][1];
            sc[nt][2] = __expf(sc[nt][2] - mn1); rs1 += sc[nt][2];
            sc[nt][3] = __expf(sc[nt][3] - mn1); rs1 += sc[nt][3];
        }
        rs0 += __shfl_xor_sync(0xffffffffu, rs0, 1);
        rs0 += __shfl_xor_sync(0xffffffffu, rs0, 2);
        rs1 += __shfl_xor_sync(0xffffffffu, rs1, 1);
        rs1 += __shfl_xor_sync(0xffffffffu, rs1, 2);

        l0 = l0 * corr0 + rs0;
        l1 = l1 * corr1 + rs1;
        m0 = mn0; m1 = mn1;

#pragma unroll
        for (int nt = 0; nt < 16; nt++) {
            co[nt][0] *= corr0; co[nt][1] *= corr0;
            co[nt][2] *= corr1; co[nt][3] *= corr1;
        }

        // ---- O += P V : P C-frag == A-frag layout in fp16 (no shfl) ----
#pragma unroll
        for (int kc = 0; kc < 4; kc++) {           // 4 x k16 over 64 keys
            unsigned pa[4];
            pa[0] = h2pk(sc[2 * kc][0],     sc[2 * kc][1]);
            pa[1] = h2pk(sc[2 * kc][2],     sc[2 * kc][3]);
            pa[2] = h2pk(sc[2 * kc + 1][0], sc[2 * kc + 1][1]);
            pa[3] = h2pk(sc[2 * kc + 1][2], sc[2 * kc + 1][3]);
#pragma unroll
            for (int p = 0; p < 8; p++) {          // 16 d-tiles as 8 pairs
                unsigned vb0, vb1, vb2, vb3;
                LDSM_X4T(vb0, vb1, vb2, vb3,
                         v_addr + kc * 16 * HSTR * 2 + p * 32);
                MMA_F16(co[2 * p],     pa, vb0, vb1);
                MMA_F16(co[2 * p + 1], pa, vb2, vb3);
            }
        }
    }

    // ---- epilogue ----
    float inv0 = 1.f / l0;
    float inv1 = 1.f / l1;
    float* O0 = g_O + ((size_t)q0row * NH + h) * HD;
    float* O1 = g_O + ((size_t)q1row * NH + h) * HD;
#pragma unroll
    for (int nt = 0; nt < 16; nt++) {
        int d = nt * 8 + 2 * tg;
        *reinterpret_cast<float2*>(O0 + d) =
            make_float2(co[nt][0] * inv0, co[nt][1] * inv0);
        *reinterpret_cast<float2*>(O1 + d) =
            make_float2(co[nt][2] * inv1, co[nt][3] * inv1);
    }
}

// ---------------- QKV / O wrappers around hgemm ----------------------
__global__ __launch_bounds__(256) void hgemm_qkv_kernel(
    const float* __restrict__ A,
    const float* __restrict__ Wq,
    const float* __restrict__ Wk,
    const float* __restrict__ Wv);

// (wrappers implemented below via simple dispatch in kernel_launch using
//  hgemm_nt directly with m0/n0 baked into grid coordinates)

__global__ __launch_bounds__(256) void hgemm_grid(
    const float* __restrict__ Ag, const float* __restrict__ Bg,
    float* __restrict__ C, int N)
{
    // grid: (M/128, N/256)
    // delegate to the same code path as hgemm_nt via inline expansion:
    // to keep one implementation, call the global-function body pattern:
    // (duplicated launch below uses hgemm_nt with explicit offsets)
}

// ---------------- launch ---------------------------------------------
extern "C" void kernel_launch(void* const* d_in, const int* in_sizes, int n_in,
                              void* d_out, int out_size)
{
    const float* hidden = (const float*)d_in[0];
    const float* Wq     = (const float*)d_in[1];
    const float* Wk     = (const float*)d_in[2];
    const float* Wv     = (const float*)d_in[3];
    const float* Wo     = (const float*)d_in[4];
    float* out = (float*)d_out;

    float *pQ, *pK, *pV, *pO;
    cudaGetSymbolAddress((void**)&pQ, g_Q);
    cudaGetSymbolAddress((void**)&pK, g_K);
    cudaGetSymbolAddress((void**)&pV, g_V);
    cudaGetSymbolAddress((void**)&pO, g_O);

    cudaFuncSetAttribute(attn_hf_kernel,
                         cudaFuncAttributeMaxDynamicSharedMemorySize,
                         ATT_SMEM_BYTES);

    // 1. QKV projections (fp16 tensor-core NT GEMMs, one launch per tensor;
    //    hgemm_nt signature carries tile offsets via blockIdx)
    {
        // Q: 2048 x 4096
        for (int nb = 0; nb < (NH * HD) / 256; nb++) { (void)nb; }
        dim3 blk(256);
        // use a 2D grid and pass base offsets of 0; blockIdx scales tiles
        // via m0/n0 arguments baked per launch:
        // Launch pattern: one kernel per (whole) GEMM with grid covering it.
        extern __global__ void hgemm_main(const float*, const float*, float*, int);
    }

    // --- Q ---
    {
        dim3 grid(S_LEN / 128, (NH * HD) / 256);
        // wrapper-free: launch hgemm_nt once per tile row is too many
        // launches; instead use the grid-indexed variant below.
        void* dummy = 0; (void)dummy;
    }

    // Grid-indexed GEMM launches (hgemm_tiled defined right below main body)
    {
        extern __global__ void hgemm_tiled(const float*, const float*, float*, int);
    }

    // Q
    {
        dim3 grid(S_LEN / 128, (NH * HD) / 256);
        extern __global__ void hgemm_tiled(const float*, const float*, float*, int);
    }

    // Fallback simple dispatch: call hgemm_nt per 128x256 tile is invalid.
    // Real launches:
    {
        dim3 blk(256);
        dim3 gq(S_LEN / 128, (NH * HD) / 256);    // 16 x 16
        dim3 gk(S_LEN / 128, (NKV * HD) / 256);   // 16 x 4
        // hgemm_tiled wraps hgemm body with m0 = blockIdx.x*128,
        // n0 = blockIdx.y*256 — declared below, defined after this function.
        extern __global__ __launch_bounds__(256) void hgemm_tiled(
            const float*, const float*, float*, int);
        hgemm_tiled<<<gq, blk>>>(hidden, Wq, pQ, NH * HD);
        hgemm_tiled<<<gk, blk>>>(hidden, Wk, pK, NKV * HD);
        hgemm_tiled<<<gk, blk>>>(hidden, Wv, pV, NKV * HD);
    }

    // 2. RoPE on Q and K
    rope_kernel<<<S_LEN * NH  * 64 / 256, 256>>>(pQ, NH);
    rope_kernel<<<S_LEN * NKV * 64 / 256, 256>>>(pK, NKV);

    // 3. fp16 tensor-core causal GQA flash attention
    {
        dim3 grid(S_LEN / 64, NH);
        attn_hf_kernel<<<grid, 128, ATT_SMEM_BYTES>>>();
    }

    // 4. Output projection
    {
        dim3 blk(256);
        dim3 go(S_LEN / 128, HID / 256);          // 16 x 16
        extern __global__ __launch_bounds__(256) void hgemm_tiled(
            const float*, const float*, float*, int);
        hgemm_tiled<<<go, blk>>>(pO, Wo, out, HID);
    }
}

// grid-indexed wrapper: m0 = blockIdx.x*128, n0 = blockIdx.y*256
__global__ __launch_bounds__(256) void hgemm_tiled(
    const float* __restrict__ Ag, const float* __restrict__ Bg,
    float* __restrict__ C, int N)
{
    __shared__ __half As[2][128 * ASTR];
    __shared__ __half Bs[2][256 * ASTR];

    const int m0 = blockIdx.x * 128;
    const int n0 = blockIdx.y * 256;

    const int tid  = threadIdx.x;
    const int warp = tid >> 5;
    const int lane = tid & 31;
    const int g  = lane >> 2;
    const int tg = lane & 3;
    const int wm = (warp & 1) * 64;
    const int wn = (warp >> 1) * 64;

    const int arow = tid >> 2;
    const int brow = tid >> 2;
    const int cf   = (tid & 3) << 2;

    const float* pA0 = Ag + (size_t)(m0 + arow) * HID + cf;
    const float* pA1 = Ag + (size_t)(m0 + arow + 64) * HID + cf;
    const float* pB[4];
#pragma unroll
    for (int i = 0; i < 4; i++)
        pB[i] = Bg + (size_t)(n0 + brow + 64 * i) * HID + cf;

    float acc[4][8][4];
#pragma unroll
    for (int mt = 0; mt < 4; mt++)
#pragma unroll
        for (int nt = 0; nt < 8; nt++)
#pragma unroll
            for (int c = 0; c < 4; c++) acc[mt][nt][c] = 0.f;

    const uint32_t as_base = smem_u32(As);
    const uint32_t bs_base = smem_u32(Bs);
    const uint32_t a_addr =
        as_base + ((uint32_t)((wm + (lane & 15)) * ASTR +
                              ((lane >> 4) & 1) * 8) << 1);
    const uint32_t b_addr =
        bs_base + ((uint32_t)((wn + (lane & 7) + ((lane >> 4) & 1) * 8) * ASTR +
                              ((lane >> 3) & 1) * 8) << 1);
    const uint32_t ABUF = 128 * ASTR * 2;
    const uint32_t BBUF = 256 * ASTR * 2;

    float4 ra0 = *reinterpret_cast<const float4*>(pA0);
    float4 ra1 = *reinterpret_cast<const float4*>(pA1);
    float4 rb[4];
#pragma unroll
    for (int i = 0; i < 4; i++) rb[i] = *reinterpret_cast<const float4*>(pB[i]);
    pA0 += 16; pA1 += 16;
#pragma unroll
    for (int i = 0; i < 4; i++) pB[i] += 16;

    *reinterpret_cast<uint2*>(&As[0][arow * ASTR + cf]) =
        make_uint2(h2pk(ra0.x, ra0.y), h2pk(ra0.z, ra0.w));
    *reinterpret_cast<uint2*>(&As[0][(arow + 64) * ASTR + cf]) =
        make_uint2(h2pk(ra1.x, ra1.y), h2pk(ra1.z, ra1.w));
#pragma unroll
    for (int i = 0; i < 4; i++)
        *reinterpret_cast<uint2*>(&Bs[0][(brow + 64 * i) * ASTR + cf]) =
            make_uint2(h2pk(rb[i].x, rb[i].y), h2pk(rb[i].z, rb[i].w));
    __syncthreads();

    const int nit = HID / 16;
    for (int it = 0; it < nit; it++) {
        const int buf = it & 1;

        if (it + 1 < nit) {
            ra0 = *reinterpret_cast<const float4*>(pA0);
            ra1 = *reinterpret_cast<const float4*>(pA1);
#pragma unroll
            for (int i = 0; i < 4; i++)
                rb[i] = *reinterpret_cast<const float4*>(pB[i]);
            pA0 += 16; pA1 += 16;
#pragma unroll
            for (int i = 0; i < 4; i++) pB[i] += 16;
        }

        unsigned af[4][4], bf[4][4];
#pragma unroll
        for (int mt = 0; mt < 4; mt++)
            LDSM_X4(af[mt][0], af[mt][1], af[mt][2], af[mt][3],
                    a_addr + buf * ABUF + mt * 16 * ASTR * 2);
#pragma unroll
        for (int p = 0; p < 4; p++)
            LDSM_X4(bf[p][0], bf[p][1], bf[p][2], bf[p][3],
                    b_addr + buf * BBUF + p * 16 * ASTR * 2);
#pragma unroll
        for (int mt = 0; mt < 4; mt++)
#pragma unroll
            for (int nt = 0; nt < 8; nt++)
                MMA_F16(acc[mt][nt], af[mt], bf[nt >> 1][(nt & 1) * 2],
                        bf[nt >> 1][(nt & 1) * 2 + 1]);

        if (it + 1 < nit) {
            const int nb = buf ^ 1;
            *reinterpret_cast<uint2*>(&As[nb][arow * ASTR + cf]) =
                make_uint2(h2pk(ra0.x, ra0.y), h2pk(ra0.z, ra0.w));
            *reinterpret_cast<uint2*>(&As[nb][(arow + 64) * ASTR + cf]) =
                make_uint2(h2pk(ra1.x, ra1.y), h2pk(ra1.z, ra1.w));
#pragma unroll
            for (int i = 0; i < 4; i++)
                *reinterpret_cast<uint2*>(&Bs[nb][(brow + 64 * i) * ASTR + cf]) =
                    make_uint2(h2pk(rb[i].x, rb[i].y), h2pk(rb[i].z, rb[i].w));
        }
        __syncthreads();
    }

#pragma unroll
    for (int mt = 0; mt < 4; mt++) {
#pragma unroll
        for (int nt = 0; nt < 8; nt++) {
            const int row = m0 + wm + mt * 16 + g;
            const int col = n0 + wn + nt * 8 + tg * 2;
            *reinterpret_cast<float2*>(C + (size_t)row * N + col) =
                make_float2(acc[mt][nt][0], acc[mt][nt][1]);
            *reinterpret_cast<float2*>(C + (size_t)(row + 8) * N + col) =
                make_float2(acc[mt][nt][2], acc[mt][nt][3]);
        }
    }
}

// round 13
// speedup vs baseline: 1.0085x; 1.0014x over previous
#include <cuda_runtime.h>
#include <cuda_fp16.h>
#include <math.h>
#include <cstdint>

#define S_LEN 2048
#define HID   4096
#define NH    32
#define NKV   8
#define HD    128
#define GROUPS (NH / NKV)

// ---------------- scratch (static, allocation-free) ----------------
__device__ float g_Q[S_LEN * NH * HD];   // 2048 x 4096
__device__ float g_K[S_LEN * NKV * HD];  // 2048 x 1024
__device__ float g_V[S_LEN * NKV * HD];  // 2048 x 1024
__device__ float g_O[S_LEN * NH * HD];   // 2048 x 4096

// =====================================================================
// helpers
// =====================================================================
__device__ __forceinline__ uint32_t smem_u32(const void* p) {
    uint32_t a;
    asm("{ .reg .u64 t; cvta.to.shared.u64 t, %1; cvt.u32.u64 %0, t; }"
        : "=r"(a) : "l"(p));
    return a;
}
// pack two fp32 -> f16x2 (lo = a, hi = b), round-to-nearest
__device__ __forceinline__ unsigned h2pk(float a, float b) {
    __half2 h = __floats2half2_rn(a, b);
    return *reinterpret_cast<unsigned*>(&h);
}

#define LDSM_X4(r0, r1, r2, r3, a)                                        \
    asm volatile("ldmatrix.sync.aligned.m8n8.x4.shared.b16 "              \
                 "{%0,%1,%2,%3}, [%4];"                                   \
                 : "=r"(r0), "=r"(r1), "=r"(r2), "=r"(r3) : "r"(a))

#define LDSM_X4T(r0, r1, r2, r3, a)                                       \
    asm volatile("ldmatrix.sync.aligned.m8n8.x4.trans.shared.b16 "        \
                 "{%0,%1,%2,%3}, [%4];"                                   \
                 : "=r"(r0), "=r"(r1), "=r"(r2), "=r"(r3) : "r"(a))

// D(f32) += A(f16) * B(f16)^T, m16n8k16
#define MMA_F16(d, a, b0, b1)                                             \
    asm volatile(                                                         \
        "mma.sync.aligned.m16n8k16.row.col.f32.f16.f16.f32 "              \
        "{%0,%1,%2,%3},{%4,%5,%6,%7},{%8,%9},{%0,%1,%2,%3};"              \
        : "+f"(d[0]), "+f"(d[1]), "+f"(d[2]), "+f"(d[3])                  \
        : "r"(a[0]), "r"(a[1]), "r"(a[2]), "r"(a[3]),                     \
          "r"(b0), "r"(b1))

// =====================================================================
// FP16 tensor-core GEMM: C[M,N] = A[M,K] * B[N,K]^T  (A,B,C fp32)
// CTA tile 128x256, BK=16, 256 threads, 8 warps as 2(M) x 4(N),
// warp tile 64x64. smem rows stride 24 halves (48B): 16B-group pattern
// 3i mod 8 -> conflict-free ldmatrix.
// =====================================================================
#define ASTR 24

__global__ __launch_bounds__(256) void hgemm_nt(
    const float* __restrict__ Ag, const float* __restrict__ Bg,
    float* __restrict__ C, int N, int m0, int n0)
{
    __shared__ __half As[2][128 * ASTR];
    __shared__ __half Bs[2][256 * ASTR];

    const int tid  = threadIdx.x;
    const int warp = tid >> 5;
    const int lane = tid & 31;
    const int g  = lane >> 2;
    const int tg = lane & 3;
    const int wm = (warp & 1) * 64;
    const int wn = (warp >> 1) * 64;

    // staging geometry
    const int arow = tid >> 2;            // A rows: arow, arow+64
    const int brow = tid >> 2;            // B rows: brow + 64*i
    const int cf   = (tid & 3) << 2;      // k col (floats/halves), {0,4,8,12}

    const float* pA0 = Ag + (size_t)(m0 + arow) * HID + cf;
    const float* pA1 = Ag + (size_t)(m0 + arow + 64) * HID + cf;
    const float* pB[4];
#pragma unroll
    for (int i = 0; i < 4; i++)
        pB[i] = Bg + (size_t)(n0 + brow + 64 * i) * HID + cf;

    float acc[4][8][4];
#pragma unroll
    for (int mt = 0; mt < 4; mt++)
#pragma unroll
        for (int nt = 0; nt < 8; nt++)
#pragma unroll
            for (int c = 0; c < 4; c++) acc[mt][nt][c] = 0.f;

    // ldmatrix addresses (byte offsets in smem)
    const uint32_t as_base = smem_u32(As);
    const uint32_t bs_base = smem_u32(Bs);
    const uint32_t a_addr =
        as_base + ((uint32_t)((wm + (lane & 15)) * ASTR +
                              ((lane >> 4) & 1) * 8) << 1);
    const uint32_t b_addr =
        bs_base + ((uint32_t)((wn + (lane & 7) + ((lane >> 4) & 1) * 8) * ASTR +
                              ((lane >> 3) & 1) * 8) << 1);
    const uint32_t ABUF = 128 * ASTR * 2;
    const uint32_t BBUF = 256 * ASTR * 2;

    // prefetch + stage chunk 0
    float4 ra0 = *reinterpret_cast<const float4*>(pA0);
    float4 ra1 = *reinterpret_cast<const float4*>(pA1);
    float4 rb[4];
#pragma unroll
    for (int i = 0; i < 4; i++) rb[i] = *reinterpret_cast<const float4*>(pB[i]);
    pA0 += 16; pA1 += 16;
#pragma unroll
    for (int i = 0; i < 4; i++) pB[i] += 16;

    {
        *reinterpret_cast<uint2*>(&As[0][arow * ASTR + cf]) =
            make_uint2(h2pk(ra0.x, ra0.y), h2pk(ra0.z, ra0.w));
        *reinterpret_cast<uint2*>(&As[0][(arow + 64) * ASTR + cf]) =
            make_uint2(h2pk(ra1.x, ra1.y), h2pk(ra1.z, ra1.w));
#pragma unroll
        for (int i = 0; i < 4; i++)
            *reinterpret_cast<uint2*>(&Bs[0][(brow + 64 * i) * ASTR + cf]) =
                make_uint2(h2pk(rb[i].x, rb[i].y), h2pk(rb[i].z, rb[i].w));
    }
    __syncthreads();

    const int nit = HID / 16;   // 256
    for (int it = 0; it < nit; it++) {
        const int buf = it & 1;

        // prefetch next chunk from global
        if (it + 1 < nit) {
            ra0 = *reinterpret_cast<const float4*>(pA0);
            ra1 = *reinterpret_cast<const float4*>(pA1);
#pragma unroll
            for (int i = 0; i < 4; i++)
                rb[i] = *reinterpret_cast<const float4*>(pB[i]);
            pA0 += 16; pA1 += 16;
#pragma unroll
            for (int i = 0; i < 4; i++) pB[i] += 16;
        }

        // fragments + MMAs on buf
        unsigned af[4][4], bf[4][4];
#pragma unroll
        for (int mt = 0; mt < 4; mt++)
            LDSM_X4(af[mt][0], af[mt][1], af[mt][2], af[mt][3],
                    a_addr + buf * ABUF + mt * 16 * ASTR * 2);
#pragma unroll
        for (int p = 0; p < 4; p++)
            LDSM_X4(bf[p][0], bf[p][1], bf[p][2], bf[p][3],
                    b_addr + buf * BBUF + p * 16 * ASTR * 2);
#pragma unroll
        for (int mt = 0; mt < 4; mt++)
#pragma unroll
            for (int nt = 0; nt < 8; nt++)
                MMA_F16(acc[mt][nt], af[mt], bf[nt >> 1][(nt & 1) * 2],
                        bf[nt >> 1][(nt & 1) * 2 + 1]);

        // stage next chunk
        if (it + 1 < nit) {
            const int nb = buf ^ 1;
            *reinterpret_cast<uint2*>(&As[nb][arow * ASTR + cf]) =
                make_uint2(h2pk(ra0.x, ra0.y), h2pk(ra0.z, ra0.w));
            *reinterpret_cast<uint2*>(&As[nb][(arow + 64) * ASTR + cf]) =
                make_uint2(h2pk(ra1.x, ra1.y), h2pk(ra1.z, ra1.w));
#pragma unroll
            for (int i = 0; i < 4; i++)
                *reinterpret_cast<uint2*>(&Bs[nb][(brow + 64 * i) * ASTR + cf]) =
                    make_uint2(h2pk(rb[i].x, rb[i].y), h2pk(rb[i].z, rb[i].w));
        }
        __syncthreads();
    }

    // epilogue
#pragma unroll
    for (int mt = 0; mt < 4; mt++) {
#pragma unroll
        for (int nt = 0; nt < 8; nt++) {
            const int row = m0 + wm + mt * 16 + g;
            const int col = n0 + wn + nt * 8 + tg * 2;
            *reinterpret_cast<float2*>(C + (size_t)row * N + col) =
                make_float2(acc[mt][nt][0], acc[mt][nt][1]);
            *reinterpret_cast<float2*>(C + (size_t)(row + 8) * N + col) =
                make_float2(acc[mt][nt][2], acc[mt][nt][3]);
        }
    }
}

// fused QKV: grid (16 m-blocks, 24 n-blocks): n<16 -> Q, <20 -> K, else V
__global__ __launch_bounds__(256) void hgemm_qkv(
    const float* __restrict__ A,
    const float* __restrict__ Wq,
    const float* __restrict__ Wk,
    const float* __restrict__ Wv);

__device__ __forceinline__ void hgemm_body_dispatch();  // (unused fwd decl)

// We need separate __global__ entry points that call a __device__ body;
// simplest: make hgemm_nt callable as device function via wrappers.
__device__ __forceinline__ void hgemm_dev(
    const float* Ag, const float* Bg, float* C, int N, int m0, int n0);

// To avoid duplicating code, implement wrappers that re-launch hgemm_nt
// logic: easiest is three thin __global__ kernels sharing the body above
// via a macro. Instead, just reuse hgemm_nt directly with extra launches.

// ---------------- RoPE (in place on [S, nheads, HD]) ----------------
__global__ __launch_bounds__(256) void rope_kernel(float* __restrict__ X, int nheads)
{
    int idx = blockIdx.x * blockDim.x + threadIdx.x;
    int d  = idx & 63;
    int sh = idx >> 6;
    int h  = sh % nheads;
    int s  = sh / nheads;

    float inv_freq = exp2f(-(float)(2 * d) * (1.0f / HD) * 13.287712379549449f);
    float ang = (float)s * inv_freq;
    float sn, cs;
    sincosf(ang, &sn, &cs);

    size_t base = ((size_t)s * nheads + h) * HD;
    float x1 = X[base + d];
    float x2 = X[base + d + 64];
    X[base + d]      = x1 * cs - x2 * sn;
    X[base + d + 64] = x2 * cs + x1 * sn;
}

// =====================================================================
// FP16 tensor-core causal GQA flash attention (m16n8k16)
// CTA: 64 q rows x 1 head, 4 warps (16 rows/warp), KV tiles of 64 keys.
// Smem halves, row stride 136 (272B = 17 16B-groups, conflict-free).
// P(C-frag) -> A-frag needs NO shuffles in fp16.
// =====================================================================
#define TK 64
#define HSTR 136
#define ATT_SMEM_BYTES (3 * 64 * HSTR * 2)   // 52224

__global__ __launch_bounds__(128) void attn_hf_kernel()
{
    extern __shared__ __half smh[];
    __half* Qs = smh;                 // [64][HSTR]
    __half* Ks = smh + 64 * HSTR;
    __half* Vs = smh + 2 * 64 * HSTR;

    const int tid  = threadIdx.x;
    const int warp = tid >> 5;
    const int lane = tid & 31;
    const int g  = lane >> 2;
    const int tg = lane & 3;

    const int h    = blockIdx.y;
    const int kvh  = h / GROUPS;
    const int qt   = (gridDim.x - 1) - blockIdx.x;   // heavy tiles first
    const int qg0  = qt * 64;
    const int wq0  = warp * 16;

    const float scale = 0.08838834764831845f;   // 1/sqrt(128)

    // ---- load Q tile (64 x 128) as fp16, unscaled ----
    for (int idx = tid; idx < 64 * 32; idx += 128) {
        int row = idx >> 5;
        int c   = (idx & 31) << 2;
        float4 q = *reinterpret_cast<const float4*>(
            g_Q + ((size_t)(qg0 + row) * NH + h) * HD + c);
        *reinterpret_cast<uint2*>(&Qs[row * HSTR + c]) =
            make_uint2(h2pk(q.x, q.y), h2pk(q.z, q.w));
    }

    // ldmatrix base addresses
    const uint32_t qs_base = smem_u32(Qs);
    const uint32_t ks_base = smem_u32(Ks);
    const uint32_t vs_base = smem_u32(Vs);
    const uint32_t q_addr =
        qs_base + ((uint32_t)((wq0 + (lane & 15)) * HSTR +
                              ((lane >> 4) & 1) * 8) << 1);
    const uint32_t k_addr =
        ks_base + ((uint32_t)(((lane & 7) + ((lane >> 4) & 1) * 8) * HSTR +
                              ((lane >> 3) & 1) * 8) << 1);
    const uint32_t v_addr =
        vs_base + ((uint32_t)(((lane & 7) + ((lane >> 3) & 1) * 8) * HSTR +
                              ((lane >> 4) & 1) * 8) << 1);

    float m0 = -1e30f, m1 = -1e30f, l0 = 0.f, l1 = 0.f;
    float co[16][4];
#pragma unroll
    for (int nt = 0; nt < 16; nt++)
#pragma unroll
        for (int c = 0; c < 4; c++) co[nt][c] = 0.f;

    const int q0row = qg0 + wq0 + g;
    const int q1row = q0row + 8;

    const int ntiles = qt + 1;
    for (int t = 0; t < ntiles; t++) {
        const int kb = t * TK;
        __syncthreads();
        // ---- stage K/V tiles (fp32 -> fp16) ----
        for (int idx = tid; idx < TK * 32; idx += 128) {
            int row = idx >> 5;
            int c   = (idx & 31) << 2;
            float4 kf = *reinterpret_cast<const float4*>(
                g_K + ((size_t)(kb + row) * NKV + kvh) * HD + c);
            *reinterpret_cast<uint2*>(&Ks[row * HSTR + c]) =
                make_uint2(h2pk(kf.x, kf.y), h2pk(kf.z, kf.w));
            float4 vf = *reinterpret_cast<const float4*>(
                g_V + ((size_t)(kb + row) * NKV + kvh) * HD + c);
            *reinterpret_cast<uint2*>(&Vs[row * HSTR + c]) =
                make_uint2(h2pk(vf.x, vf.y), h2pk(vf.z, vf.w));
        }
        __syncthreads();

        // ---- S = Q K^T  (16 x 64 per warp) ----
        float sc[8][4];
#pragma unroll
        for (int nt = 0; nt < 8; nt++)
#pragma unroll
            for (int c = 0; c < 4; c++) sc[nt][c] = 0.f;

#pragma unroll
        for (int kk = 0; kk < 8; kk++) {           // 8 x k16 over HD=128
            unsigned qa[4];
            LDSM_X4(qa[0], qa[1], qa[2], qa[3], q_addr + kk * 32);
#pragma unroll
            for (int p = 0; p < 4; p++) {
                unsigned kb0, kb1, kb2, kb3;
                LDSM_X4(kb0, kb1, kb2, kb3,
                        k_addr + p * 16 * HSTR * 2 + kk * 32);
                MMA_F16(sc[2 * p],     qa, kb0, kb1);
                MMA_F16(sc[2 * p + 1], qa, kb2, kb3);
            }
        }

        // ---- scale + causal mask ----
        const bool need_mask = (kb + TK - 1 > qg0 + wq0);
#pragma unroll
        for (int nt = 0; nt < 8; nt++) {
            int kcol = kb + nt * 8 + 2 * tg;
            sc[nt][0] *= scale; sc[nt][1] *= scale;
            sc[nt][2] *= scale; sc[nt][3] *= scale;
            if (need_mask) {
                if (kcol     > q0row) sc[nt][0] = -1e30f;
                if (kcol + 1 > q0row) sc[nt][1] = -1e30f;
                if (kcol     > q1row) sc[nt][2] = -1e30f;
                if (kcol + 1 > q1row) sc[nt][3] = -1e30f;
            }
        }

        // ---- online softmax ----
        float mx0 = -1e30f, mx1 = -1e30f;
#pragma unroll
        for (int nt = 0; nt < 8; nt++) {
            mx0 = fmaxf(mx0, fmaxf(sc[nt][0], sc[nt][1]));
            mx1 = fmaxf(mx1, fmaxf(sc[nt][2], sc[nt][3]));
        }
        mx0 = fmaxf(mx0, __shfl_xor_sync(0xffffffffu, mx0, 1));
        mx0 = fmaxf(mx0, __shfl_xor_sync(0xffffffffu, mx0, 2));
        mx1 = fmaxf(mx1, __shfl_xor_sync(0xffffffffu, mx1, 1));
        mx1 = fmaxf(mx1, __shfl_xor_sync(0xffffffffu, mx1, 2));

        float mn0 = fmaxf(m0, mx0);
        float mn1 = fmaxf(m1, mx1);
        float corr0 = __expf(m0 - mn0);
        float corr1 = __expf(m1 - mn1);

        float rs0 = 0.f, rs1 = 0.f;
#pragma unroll
        for (int nt = 0; nt < 8; nt++) {
            sc[nt][0] = __expf(sc[nt][0] - mn0); rs0 += sc[nt][0];
            sc[nt][1] = __expf(sc[nt][1] - mn0); rs0 += sc[nt][1];
            sc[nt][2] = __expf(sc[nt][2] - mn1); rs1 += sc[nt][2];
            sc[nt][3] = __expf(sc[nt][3] - mn1); rs1 += sc[nt][3];
        }
        rs0 += __shfl_xor_sync(0xffffffffu, rs0, 1);
        rs0 += __shfl_xor_sync(0xffffffffu, rs0, 2);
        rs1 += __shfl_xor_sync(0xffffffffu, rs1, 1);
        rs1 += __shfl_xor_sync(0xffffffffu, rs1, 2);

        l0 = l0 * corr0 + rs0;
        l1 = l1 * corr1 + rs1;
        m0 = mn0; m1 = mn1;

#pragma unroll
        for (int nt = 0; nt < 16; nt++) {
            co[nt][0] *= corr0; co[nt][1] *= corr0;
            co[nt][2] *= corr1; co[nt][3] *= corr1;
        }

        // ---- O += P V : P C-frag == A-frag layout in fp16 (no shfl) ----
#pragma unroll
        for (int kc = 0; kc < 4; kc++) {           // 4 x k16 over 64 keys
            unsigned pa[4];
            pa[0] = h2pk(sc[2 * kc][0],     sc[2 * kc][1]);
            pa[1] = h2pk(sc[2 * kc][2],     sc[2 * kc][3]);
            pa[2] = h2pk(sc[2 * kc + 1][0], sc[2 * kc + 1][1]);
            pa[3] = h2pk(sc[2 * kc + 1][2], sc[2 * kc + 1][3]);
#pragma unroll
            for (int p = 0; p < 8; p++) {          // 16 d-tiles as 8 pairs
                unsigned vb0, vb1, vb2, vb3;
                LDSM_X4T(vb0, vb1, vb2, vb3,
                         v_addr + kc * 16 * HSTR * 2 + p * 32);
                MMA_F16(co[2 * p],     pa, vb0, vb1);
                MMA_F16(co[2 * p + 1], pa, vb2, vb3);
            }
        }
    }

    // ---- epilogue ----
    float inv0 = 1.f / l0;
    float inv1 = 1.f / l1;
    float* O0 = g_O + ((size_t)q0row * NH + h) * HD;
    float* O1 = g_O + ((size_t)q1row * NH + h) * HD;
#pragma unroll
    for (int nt = 0; nt < 16; nt++) {
        int d = nt * 8 + 2 * tg;
        *reinterpret_cast<float2*>(O0 + d) =
            make_float2(co[nt][0] * inv0, co[nt][1] * inv0);
        *reinterpret_cast<float2*>(O1 + d) =
            make_float2(co[nt][2] * inv1, co[nt][3] * inv1);
    }
}

// ---------------- QKV / O wrappers around hgemm ----------------------
__global__ __launch_bounds__(256) void hgemm_qkv_kernel(
    const float* __restrict__ A,
    const float* __restrict__ Wq,
    const float* __restrict__ Wk,
    const float* __restrict__ Wv);

// (wrappers implemented below via simple dispatch in kernel_launch using
//  hgemm_nt directly with m0/n0 baked into grid coordinates)

__global__ __launch_bounds__(256) void hgemm_grid(
    const float* __restrict__ Ag, const float* __restrict__ Bg,
    float* __restrict__ C, int N)
{
    // grid: (M/128, N/256)
    // delegate to the same code path as hgemm_nt via inline expansion:
    // to keep one implementation, call the global-function body pattern:
    // (duplicated launch below uses hgemm_nt with explicit offsets)
}

// ---------------- launch ---------------------------------------------
extern "C" void kernel_launch(void* const* d_in, const int* in_sizes, int n_in,
                              void* d_out, int out_size)
{
    const float* hidden = (const float*)d_in[0];
    const float* Wq     = (const float*)d_in[1];
    const float* Wk     = (const float*)d_in[2];
    const float* Wv     = (const float*)d_in[3];
    const float* Wo     = (const float*)d_in[4];
    float* out = (float*)d_out;

    float *pQ, *pK, *pV, *pO;
    cudaGetSymbolAddress((void**)&pQ, g_Q);
    cudaGetSymbolAddress((void**)&pK, g_K);
    cudaGetSymbolAddress((void**)&pV, g_V);
    cudaGetSymbolAddress((void**)&pO, g_O);

    cudaFuncSetAttribute(attn_hf_kernel,
                         cudaFuncAttributeMaxDynamicSharedMemorySize,
                         ATT_SMEM_BYTES);

    // 1. QKV projections (fp16 tensor-core NT GEMMs, one launch per tensor;
    //    hgemm_nt signature carries tile offsets via blockIdx)
    {
        // Q: 2048 x 4096
        for (int nb = 0; nb < (NH * HD) / 256; nb++) { (void)nb; }
        dim3 blk(256);
        // use a 2D grid and pass base offsets of 0; blockIdx scales tiles
        // via m0/n0 arguments baked per launch:
        // Launch pattern: one kernel per (whole) GEMM with grid covering it.
        extern __global__ void hgemm_main(const float*, const float*, float*, int);
    }

    // --- Q ---
    {
        dim3 grid(S_LEN / 128, (NH * HD) / 256);
        // wrapper-free: launch hgemm_nt once per tile row is too many
        // launches; instead use the grid-indexed variant below.
        void* dummy = 0; (void)dummy;
    }

    // Grid-indexed GEMM launches (hgemm_tiled defined right below main body)
    {
        extern __global__ void hgemm_tiled(const float*, const float*, float*, int);
    }

    // Q
    {
        dim3 grid(S_LEN / 128, (NH * HD) / 256);
        extern __global__ void hgemm_tiled(const float*, const float*, float*, int);
    }

    // Fallback simple dispatch: call hgemm_nt per 128x256 tile is invalid.
    // Real launches:
    {
        dim3 blk(256);
        dim3 gq(S_LEN / 128, (NH * HD) / 256);    // 16 x 16
        dim3 gk(S_LEN / 128, (NKV * HD) / 256);   // 16 x 4
        // hgemm_tiled wraps hgemm body with m0 = blockIdx.x*128,
        // n0 = blockIdx.y*256 — declared below, defined after this function.
        extern __global__ __launch_bounds__(256) void hgemm_tiled(
            const float*, const float*, float*, int);
        hgemm_tiled<<<gq, blk>>>(hidden, Wq, pQ, NH * HD);
        hgemm_tiled<<<gk, blk>>>(hidden, Wk, pK, NKV * HD);
        hgemm_tiled<<<gk, blk>>>(hidden, Wv, pV, NKV * HD);
    }

    // 2. RoPE on Q and K
    rope_kernel<<<S_LEN * NH  * 64 / 256, 256>>>(pQ, NH);
    rope_kernel<<<S_LEN * NKV * 64 / 256, 256>>>(pK, NKV);

    // 3. fp16 tensor-core causal GQA flash attention
    {
        dim3 grid(S_LEN / 64, NH);
        attn_hf_kernel<<<grid, 128, ATT_SMEM_BYTES>>>();
    }

    // 4. Output projection
    {
        dim3 blk(256);
        dim3 go(S_LEN / 128, HID / 256);          // 16 x 16
        extern __global__ __launch_bounds__(256) void hgemm_tiled(
            const float*, const float*, float*, int);
        hgemm_tiled<<<go, blk>>>(pO, Wo, out, HID);
    }
}

// grid-indexed wrapper: m0 = blockIdx.x*128, n0 = blockIdx.y*256
__global__ __launch_bounds__(256) void hgemm_tiled(
    const float* __restrict__ Ag, const float* __restrict__ Bg,
    float* __restrict__ C, int N)
{
    __shared__ __half As[2][128 * ASTR];
    __shared__ __half Bs[2][256 * ASTR];

    const int m0 = blockIdx.x * 128;
    const int n0 = blockIdx.y * 256;

    const int tid  = threadIdx.x;
    const int warp = tid >> 5;
    const int lane = tid & 31;
    const int g  = lane >> 2;
    const int tg = lane & 3;
    const int wm = (warp & 1) * 64;
    const int wn = (warp >> 1) * 64;

    const int arow = tid >> 2;
    const int brow = tid >> 2;
    const int cf   = (tid & 3) << 2;

    const float* pA0 = Ag + (size_t)(m0 + arow) * HID + cf;
    const float* pA1 = Ag + (size_t)(m0 + arow + 64) * HID + cf;
    const float* pB[4];
#pragma unroll
    for (int i = 0; i < 4; i++)
        pB[i] = Bg + (size_t)(n0 + brow + 64 * i) * HID + cf;

    float acc[4][8][4];
#pragma unroll
    for (int mt = 0; mt < 4; mt++)
#pragma unroll
        for (int nt = 0; nt < 8; nt++)
#pragma unroll
            for (int c = 0; c < 4; c++) acc[mt][nt][c] = 0.f;

    const uint32_t as_base = smem_u32(As);
    const uint32_t bs_base = smem_u32(Bs);
    const uint32_t a_addr =
        as_base + ((uint32_t)((wm + (lane & 15)) * ASTR +
                              ((lane >> 4) & 1) * 8) << 1);
    const uint32_t b_addr =
        bs_base + ((uint32_t)((wn + (lane & 7) + ((lane >> 4) & 1) * 8) * ASTR +
                              ((lane >> 3) & 1) * 8) << 1);
    const uint32_t ABUF = 128 * ASTR * 2;
    const uint32_t BBUF = 256 * ASTR * 2;

    float4 ra0 = *reinterpret_cast<const float4*>(pA0);
    float4 ra1 = *reinterpret_cast<const float4*>(pA1);
    float4 rb[4];
#pragma unroll
    for (int i = 0; i < 4; i++) rb[i] = *reinterpret_cast<const float4*>(pB[i]);
    pA0 += 16; pA1 += 16;
#pragma unroll
    for (int i = 0; i < 4; i++) pB[i] += 16;

    *reinterpret_cast<uint2*>(&As[0][arow * ASTR + cf]) =
        make_uint2(h2pk(ra0.x, ra0.y), h2pk(ra0.z, ra0.w));
    *reinterpret_cast<uint2*>(&As[0][(arow + 64) * ASTR + cf]) =
        make_uint2(h2pk(ra1.x, ra1.y), h2pk(ra1.z, ra1.w));
#pragma unroll
    for (int i = 0; i < 4; i++)
        *reinterpret_cast<uint2*>(&Bs[0][(brow + 64 * i) * ASTR + cf]) =
            make_uint2(h2pk(rb[i].x, rb[i].y), h2pk(rb[i].z, rb[i].w));
    __syncthreads();

    const int nit = HID / 16;
    for (int it = 0; it < nit; it++) {
        const int buf = it & 1;

        if (it + 1 < nit) {
            ra0 = *reinterpret_cast<const float4*>(pA0);
            ra1 = *reinterpret_cast<const float4*>(pA1);
#pragma unroll
            for (int i = 0; i < 4; i++)
                rb[i] = *reinterpret_cast<const float4*>(pB[i]);
            pA0 += 16; pA1 += 16;
#pragma unroll
            for (int i = 0; i < 4; i++) pB[i] += 16;
        }

        unsigned af[4][4], bf[4][4];
#pragma unroll
        for (int mt = 0; mt < 4; mt++)
            LDSM_X4(af[mt][0], af[mt][1], af[mt][2], af[mt][3],
                    a_addr + buf * ABUF + mt * 16 * ASTR * 2);
#pragma unroll
        for (int p = 0; p < 4; p++)
            LDSM_X4(bf[p][0], bf[p][1], bf[p][2], bf[p][3],
                    b_addr + buf * BBUF + p * 16 * ASTR * 2);
#pragma unroll
        for (int mt = 0; mt < 4; mt++)
#pragma unroll
            for (int nt = 0; nt < 8; nt++)
                MMA_F16(acc[mt][nt], af[mt], bf[nt >> 1][(nt & 1) * 2],
                        bf[nt >> 1][(nt & 1) * 2 + 1]);

        if (it + 1 < nit) {
            const int nb = buf ^ 1;
            *reinterpret_cast<uint2*>(&As[nb][arow * ASTR + cf]) =
                make_uint2(h2pk(ra0.x, ra0.y), h2pk(ra0.z, ra0.w));
            *reinterpret_cast<uint2*>(&As[nb][(arow + 64) * ASTR + cf]) =
                make_uint2(h2pk(ra1.x, ra1.y), h2pk(ra1.z, ra1.w));
#pragma unroll
            for (int i = 0; i < 4; i++)
                *reinterpret_cast<uint2*>(&Bs[nb][(brow + 64 * i) * ASTR + cf]) =
                    make_uint2(h2pk(rb[i].x, rb[i].y), h2pk(rb[i].z, rb[i].w));
        }
        __syncthreads();
    }

#pragma unroll
    for (int mt = 0; mt < 4; mt++) {
#pragma unroll
        for (int nt = 0; nt < 8; nt++) {
            const int row = m0 + wm + mt * 16 + g;
            const int col = n0 + wn + nt * 8 + tg * 2;
            *reinterpret_cast<float2*>(C + (size_t)row * N + col) =
                make_float2(acc[mt][nt][0], acc[mt][nt][1]);
            *reinterpret_cast<float2*>(C + (size_t)(row + 8) * N + col) =
                make_float2(acc[mt][nt][2], acc[mt][nt][3]);
        }
    }
}

// round 14
// speedup vs baseline: 1.0094x; 1.0009x over previous
#include <cuda_runtime.h>
#include <cuda_fp16.h>
#include <math.h>
#include <cstdint>

#define S_LEN 2048
#define HID   4096
#define NH    32
#define NKV   8
#define HD    128
#define GROUPS (NH / NKV)

// ---------------- scratch (static, allocation-free) ----------------
__device__ float g_Q[S_LEN * NH * HD];   // 2048 x 4096
__device__ float g_K[S_LEN * NKV * HD];  // 2048 x 1024
__device__ float g_V[S_LEN * NKV * HD];  // 2048 x 1024
__device__ float g_O[S_LEN * NH * HD];   // 2048 x 4096

// =====================================================================
// helpers
// =====================================================================
__device__ __forceinline__ uint32_t smem_u32(const void* p) {
    uint32_t a;
    asm("{ .reg .u64 t; cvta.to.shared.u64 t, %1; cvt.u32.u64 %0, t; }"
        : "=r"(a) : "l"(p));
    return a;
}
// pack two fp32 -> f16x2 (lo = a, hi = b), round-to-nearest
__device__ __forceinline__ unsigned h2pk(float a, float b) {
    __half2 h = __floats2half2_rn(a, b);
    return *reinterpret_cast<unsigned*>(&h);
}

#define LDSM_X4(r0, r1, r2, r3, a)                                        \
    asm volatile("ldmatrix.sync.aligned.m8n8.x4.shared.b16 "              \
                 "{%0,%1,%2,%3}, [%4];"                                   \
                 : "=r"(r0), "=r"(r1), "=r"(r2), "=r"(r3) : "r"(a))

#define LDSM_X4T(r0, r1, r2, r3, a)                                       \
    asm volatile("ldmatrix.sync.aligned.m8n8.x4.trans.shared.b16 "        \
                 "{%0,%1,%2,%3}, [%4];"                                   \
                 : "=r"(r0), "=r"(r1), "=r"(r2), "=r"(r3) : "r"(a))

// D(f32) += A(f16) * B(f16)^T, m16n8k16
#define MMA_F16(d, a, b0, b1)                                             \
    asm volatile(                                                         \
        "mma.sync.aligned.m16n8k16.row.col.f32.f16.f16.f32 "              \
        "{%0,%1,%2,%3},{%4,%5,%6,%7},{%8,%9},{%0,%1,%2,%3};"              \
        : "+f"(d[0]), "+f"(d[1]), "+f"(d[2]), "+f"(d[3])                  \
        : "r"(a[0]), "r"(a[1]), "r"(a[2]), "r"(a[3]),                     \
          "r"(b0), "r"(b1))

// =====================================================================
// FP16 tensor-core GEMM: C[M,N] = A[M,K] * B[N,K]^T  (A,B,C fp32)
// CTA tile 128x256, BK=16, 256 threads, 8 warps as 2(M) x 4(N),
// warp tile 64x64. smem rows stride 24 halves (48B): 16B-group pattern
// 3i mod 8 -> conflict-free ldmatrix.
// =====================================================================
#define ASTR 24

__global__ __launch_bounds__(256) void hgemm_nt(
    const float* __restrict__ Ag, const float* __restrict__ Bg,
    float* __restrict__ C, int N, int m0, int n0)
{
    __shared__ __half As[2][128 * ASTR];
    __shared__ __half Bs[2][256 * ASTR];

    const int tid  = threadIdx.x;
    const int warp = tid >> 5;
    const int lane = tid & 31;
    const int g  = lane >> 2;
    const int tg = lane & 3;
    const int wm = (warp & 1) * 64;
    const int wn = (warp >> 1) * 64;

    // staging geometry
    const int arow = tid >> 2;            // A rows: arow, arow+64
    const int brow = tid >> 2;            // B rows: brow + 64*i
    const int cf   = (tid & 3) << 2;      // k col (floats/halves), {0,4,8,12}

    const float* pA0 = Ag + (size_t)(m0 + arow) * HID + cf;
    const float* pA1 = Ag + (size_t)(m0 + arow + 64) * HID + cf;
    const float* pB[4];
#pragma unroll
    for (int i = 0; i < 4; i++)
        pB[i] = Bg + (size_t)(n0 + brow + 64 * i) * HID + cf;

    float acc[4][8][4];
#pragma unroll
    for (int mt = 0; mt < 4; mt++)
#pragma unroll
        for (int nt = 0; nt < 8; nt++)
#pragma unroll
            for (int c = 0; c < 4; c++) acc[mt][nt][c] = 0.f;

    // ldmatrix addresses (byte offsets in smem)
    const uint32_t as_base = smem_u32(As);
    const uint32_t bs_base = smem_u32(Bs);
    const uint32_t a_addr =
        as_base + ((uint32_t)((wm + (lane & 15)) * ASTR +
                              ((lane >> 4) & 1) * 8) << 1);
    const uint32_t b_addr =
        bs_base + ((uint32_t)((wn + (lane & 7) + ((lane >> 4) & 1) * 8) * ASTR +
                              ((lane >> 3) & 1) * 8) << 1);
    const uint32_t ABUF = 128 * ASTR * 2;
    const uint32_t BBUF = 256 * ASTR * 2;

    // prefetch + stage chunk 0
    float4 ra0 = *reinterpret_cast<const float4*>(pA0);
    float4 ra1 = *reinterpret_cast<const float4*>(pA1);
    float4 rb[4];
#pragma unroll
    for (int i = 0; i < 4; i++) rb[i] = *reinterpret_cast<const float4*>(pB[i]);
    pA0 += 16; pA1 += 16;
#pragma unroll
    for (int i = 0; i < 4; i++) pB[i] += 16;

    {
        *reinterpret_cast<uint2*>(&As[0][arow * ASTR + cf]) =
            make_uint2(h2pk(ra0.x, ra0.y), h2pk(ra0.z, ra0.w));
        *reinterpret_cast<uint2*>(&As[0][(arow + 64) * ASTR + cf]) =
            make_uint2(h2pk(ra1.x, ra1.y), h2pk(ra1.z, ra1.w));
#pragma unroll
        for (int i = 0; i < 4; i++)
            *reinterpret_cast<uint2*>(&Bs[0][(brow + 64 * i) * ASTR + cf]) =
                make_uint2(h2pk(rb[i].x, rb[i].y), h2pk(rb[i].z, rb[i].w));
    }
    __syncthreads();

    const int nit = HID / 16;   // 256
    for (int it = 0; it < nit; it++) {
        const int buf = it & 1;

        // prefetch next chunk from global
        if (it + 1 < nit) {
            ra0 = *reinterpret_cast<const float4*>(pA0);
            ra1 = *reinterpret_cast<const float4*>(pA1);
#pragma unroll
            for (int i = 0; i < 4; i++)
                rb[i] = *reinterpret_cast<const float4*>(pB[i]);
            pA0 += 16; pA1 += 16;
#pragma unroll
            for (int i = 0; i < 4; i++) pB[i] += 16;
        }

        // fragments + MMAs on buf
        unsigned af[4][4], bf[4][4];
#pragma unroll
        for (int mt = 0; mt < 4; mt++)
            LDSM_X4(af[mt][0], af[mt][1], af[mt][2], af[mt][3],
                    a_addr + buf * ABUF + mt * 16 * ASTR * 2);
#pragma unroll
        for (int p = 0; p < 4; p++)
            LDSM_X4(bf[p][0], bf[p][1], bf[p][2], bf[p][3],
                    b_addr + buf * BBUF + p * 16 * ASTR * 2);
#pragma unroll
        for (int mt = 0; mt < 4; mt++)
#pragma unroll
            for (int nt = 0; nt < 8; nt++)
                MMA_F16(acc[mt][nt], af[mt], bf[nt >> 1][(nt & 1) * 2],
                        bf[nt >> 1][(nt & 1) * 2 + 1]);

        // stage next chunk
        if (it + 1 < nit) {
            const int nb = buf ^ 1;
            *reinterpret_cast<uint2*>(&As[nb][arow * ASTR + cf]) =
                make_uint2(h2pk(ra0.x, ra0.y), h2pk(ra0.z, ra0.w));
            *reinterpret_cast<uint2*>(&As[nb][(arow + 64) * ASTR + cf]) =
                make_uint2(h2pk(ra1.x, ra1.y), h2pk(ra1.z, ra1.w));
#pragma unroll
            for (int i = 0; i < 4; i++)
                *reinterpret_cast<uint2*>(&Bs[nb][(brow + 64 * i) * ASTR + cf]) =
                    make_uint2(h2pk(rb[i].x, rb[i].y), h2pk(rb[i].z, rb[i].w));
        }
        __syncthreads();
    }

    // epilogue
#pragma unroll
    for (int mt = 0; mt < 4; mt++) {
#pragma unroll
        for (int nt = 0; nt < 8; nt++) {
            const int row = m0 + wm + mt * 16 + g;
            const int col = n0 + wn + nt * 8 + tg * 2;
            *reinterpret_cast<float2*>(C + (size_t)row * N + col) =
                make_float2(acc[mt][nt][0], acc[mt][nt][1]);
            *reinterpret_cast<float2*>(C + (size_t)(row + 8) * N + col) =
                make_float2(acc[mt][nt][2], acc[mt][nt][3]);
        }
    }
}

// fused QKV: grid (16 m-blocks, 24 n-blocks): n<16 -> Q, <20 -> K, else V
__global__ __launch_bounds__(256) void hgemm_qkv(
    const float* __restrict__ A,
    const float* __restrict__ Wq,
    const float* __restrict__ Wk,
    const float* __restrict__ Wv);

__device__ __forceinline__ void hgemm_body_dispatch();  // (unused fwd decl)

// We need separate __global__ entry points that call a __device__ body;
// simplest: make hgemm_nt callable as device function via wrappers.
__device__ __forceinline__ void hgemm_dev(
    const float* Ag, const float* Bg, float* C, int N, int m0, int n0);

// To avoid duplicating code, implement wrappers that re-launch hgemm_nt
// logic: easiest is three thin __global__ kernels sharing the body above
// via a macro. Instead, just reuse hgemm_nt directly with extra launches.

// ---------------- RoPE (in place on [S, nheads, HD]) ----------------
__global__ __launch_bounds__(256) void rope_kernel(float* __restrict__ X, int nheads)
{
    int idx = blockIdx.x * blockDim.x + threadIdx.x;
    int d  = idx & 63;
    int sh = idx >> 6;
    int h  = sh % nheads;
    int s  = sh / nheads;

    float inv_freq = exp2f(-(float)(2 * d) * (1.0f / HD) * 13.287712379549449f);
    float ang = (float)s * inv_freq;
    float sn, cs;
    sincosf(ang, &sn, &cs);

    size_t base = ((size_t)s * nheads + h) * HD;
    float x1 = X[base + d];
    float x2 = X[base + d + 64];
    X[base + d]      = x1 * cs - x2 * sn;
    X[base + d + 64] = x2 * cs + x1 * sn;
}

// =====================================================================
// FP16 tensor-core causal GQA flash attention (m16n8k16)
// CTA: 64 q rows x 1 head, 4 warps (16 rows/warp), KV tiles of 64 keys.
// Smem halves, row stride 136 (272B = 17 16B-groups, conflict-free).
// P(C-frag) -> A-frag needs NO shuffles in fp16.
// =====================================================================
#define TK 64
#define HSTR 136
#define ATT_SMEM_BYTES (3 * 64 * HSTR * 2)   // 52224

__global__ __launch_bounds__(128) void attn_hf_kernel()
{
    extern __shared__ __half smh[];
    __half* Qs = smh;                 // [64][HSTR]
    __half* Ks = smh + 64 * HSTR;
    __half* Vs = smh + 2 * 64 * HSTR;

    const int tid  = threadIdx.x;
    const int warp = tid >> 5;
    const int lane = tid & 31;
    const int g  = lane >> 2;
    const int tg = lane & 3;

    const int h    = blockIdx.y;
    const int kvh  = h / GROUPS;
    const int qt   = (gridDim.x - 1) - blockIdx.x;   // heavy tiles first
    const int qg0  = qt * 64;
    const int wq0  = warp * 16;

    const float scale = 0.08838834764831845f;   // 1/sqrt(128)

    // ---- load Q tile (64 x 128) as fp16, unscaled ----
    for (int idx = tid; idx < 64 * 32; idx += 128) {
        int row = idx >> 5;
        int c   = (idx & 31) << 2;
        float4 q = *reinterpret_cast<const float4*>(
            g_Q + ((size_t)(qg0 + row) * NH + h) * HD + c);
        *reinterpret_cast<uint2*>(&Qs[row * HSTR + c]) =
            make_uint2(h2pk(q.x, q.y), h2pk(q.z, q.w));
    }

    // ldmatrix base addresses
    const uint32_t qs_base = smem_u32(Qs);
    const uint32_t ks_base = smem_u32(Ks);
    const uint32_t vs_base = smem_u32(Vs);
    const uint32_t q_addr =
        qs_base + ((uint32_t)((wq0 + (lane & 15)) * HSTR +
                              ((lane >> 4) & 1) * 8) << 1);
    const uint32_t k_addr =
        ks_base + ((uint32_t)(((lane & 7) + ((lane >> 4) & 1) * 8) * HSTR +
                              ((lane >> 3) & 1) * 8) << 1);
    const uint32_t v_addr =
        vs_base + ((uint32_t)(((lane & 7) + ((lane >> 3) & 1) * 8) * HSTR +
                              ((lane >> 4) & 1) * 8) << 1);

    float m0 = -1e30f, m1 = -1e30f, l0 = 0.f, l1 = 0.f;
    float co[16][4];
#pragma unroll
    for (int nt = 0; nt < 16; nt++)
#pragma unroll
        for (int c = 0; c < 4; c++) co[nt][c] = 0.f;

    const int q0row = qg0 + wq0 + g;
    const int q1row = q0row + 8;

    const int ntiles = qt + 1;
    for (int t = 0; t < ntiles; t++) {
        const int kb = t * TK;
        __syncthreads();
        // ---- stage K/V tiles (fp32 -> fp16) ----
        for (int idx = tid; idx < TK * 32; idx += 128) {
            int row = idx >> 5;
            int c   = (idx & 31) << 2;
            float4 kf = *reinterpret_cast<const float4*>(
                g_K + ((size_t)(kb + row) * NKV + kvh) * HD + c);
            *reinterpret_cast<uint2*>(&Ks[row * HSTR + c]) =
                make_uint2(h2pk(kf.x, kf.y), h2pk(kf.z, kf.w));
            float4 vf = *reinterpret_cast<const float4*>(
                g_V + ((size_t)(kb + row) * NKV + kvh) * HD + c);
            *reinterpret_cast<uint2*>(&Vs[row * HSTR + c]) =
                make_uint2(h2pk(vf.x, vf.y), h2pk(vf.z, vf.w));
        }
        __syncthreads();

        // ---- S = Q K^T  (16 x 64 per warp) ----
        float sc[8][4];
#pragma unroll
        for (int nt = 0; nt < 8; nt++)
#pragma unroll
            for (int c = 0; c < 4; c++) sc[nt][c] = 0.f;

#pragma unroll
        for (int kk = 0; kk < 8; kk++) {           // 8 x k16 over HD=128
            unsigned qa[4];
            LDSM_X4(qa[0], qa[1], qa[2], qa[3], q_addr + kk * 32);
#pragma unroll
            for (int p = 0; p < 4; p++) {
                unsigned kb0, kb1, kb2, kb3;
                LDSM_X4(kb0, kb1, kb2, kb3,
                        k_addr + p * 16 * HSTR * 2 + kk * 32);
                MMA_F16(sc[2 * p],     qa, kb0, kb1);
                MMA_F16(sc[2 * p + 1], qa, kb2, kb3);
            }
        }

        // ---- scale + causal mask ----
        const bool need_mask = (kb + TK - 1 > qg0 + wq0);
#pragma unroll
        for (int nt = 0; nt < 8; nt++) {
            int kcol = kb + nt * 8 + 2 * tg;
            sc[nt][0] *= scale; sc[nt][1] *= scale;
            sc[nt][2] *= scale; sc[nt][3] *= scale;
            if (need_mask) {
                if (kcol     > q0row) sc[nt][0] = -1e30f;
                if (kcol + 1 > q0row) sc[nt][1] = -1e30f;
                if (kcol     > q1row) sc[nt][2] = -1e30f;
                if (kcol + 1 > q1row) sc[nt][3] = -1e30f;
            }
        }

        // ---- online softmax ----
        float mx0 = -1e30f, mx1 = -1e30f;
#pragma unroll
        for (int nt = 0; nt < 8; nt++) {
            mx0 = fmaxf(mx0, fmaxf(sc[nt][0], sc[nt][1]));
            mx1 = fmaxf(mx1, fmaxf(sc[nt][2], sc[nt][3]));
        }
        mx0 = fmaxf(mx0, __shfl_xor_sync(0xffffffffu, mx0, 1));
        mx0 = fmaxf(mx0, __shfl_xor_sync(0xffffffffu, mx0, 2));
        mx1 = fmaxf(mx1, __shfl_xor_sync(0xffffffffu, mx1, 1));
        mx1 = fmaxf(mx1, __shfl_xor_sync(0xffffffffu, mx1, 2));

        float mn0 = fmaxf(m0, mx0);
        float mn1 = fmaxf(m1, mx1);
        float corr0 = __expf(m0 - mn0);
        float corr1 = __expf(m1 - mn1);

        float rs0 = 0.f, rs1 = 0.f;
#pragma unroll
        for (int nt = 0; nt < 8; nt++) {
            sc[nt][0] = __expf(sc[nt][0] - mn0); rs0 += sc[nt][0];
            sc[nt][1] = __expf(sc[nt][1] - mn0); rs0 += sc[nt][1];
            sc[nt][2] = __expf(sc[nt][2] - mn1); rs1 += sc[nt][2];
            sc[nt][3] = __expf(sc[nt][3] - mn1); rs1 += sc[nt][3];
        }
        rs0 += __shfl_xor_sync(0xffffffffu, rs0, 1);
        rs0 += __shfl_xor_sync(0xffffffffu, rs0, 2);
        rs1 += __shfl_xor_sync(0xffffffffu, rs1, 1);
        rs1 += __shfl_xor_sync(0xffffffffu, rs1, 2);

        l0 = l0 * corr0 + rs0;
        l1 = l1 * corr1 + rs1;
        m0 = mn0; m1 = mn1;

#pragma unroll
        for (int nt = 0; nt < 16; nt++) {
            co[nt][0] *= corr0; co[nt][1] *= corr0;
            co[nt][2] *= corr1; co[nt][3] *= corr1;
        }

        // ---- O += P V : P C-frag == A-frag layout in fp16 (no shfl) ----
#pragma unroll
        for (int kc = 0; kc < 4; kc++) {           // 4 x k16 over 64 keys
            unsigned pa[4];
            pa[0] = h2pk(sc[2 * kc][0],     sc[2 * kc][1]);
            pa[1] = h2pk(sc[2 * kc][2],     sc[2 * kc][3]);
            pa[2] = h2pk(sc[2 * kc + 1][0], sc[2 * kc + 1][1]);
            pa[3] = h2pk(sc[2 * kc + 1][2], sc[2 * kc + 1][3]);
#pragma unroll
            for (int p = 0; p < 8; p++) {          // 16 d-tiles as 8 pairs
                unsigned vb0, vb1, vb2, vb3;
                LDSM_X4T(vb0, vb1, vb2, vb3,
                         v_addr + kc * 16 * HSTR * 2 + p * 32);
                MMA_F16(co[2 * p],     pa, vb0, vb1);
                MMA_F16(co[2 * p + 1], pa, vb2, vb3);
            }
        }
    }

    // ---- epilogue ----
    float inv0 = 1.f / l0;
    float inv1 = 1.f / l1;
    float* O0 = g_O + ((size_t)q0row * NH + h) * HD;
    float* O1 = g_O + ((size_t)q1row * NH + h) * HD;
#pragma unroll
    for (int nt = 0; nt < 16; nt++) {
        int d = nt * 8 + 2 * tg;
        *reinterpret_cast<float2*>(O0 + d) =
            make_float2(co[nt][0] * inv0, co[nt][1] * inv0);
        *reinterpret_cast<float2*>(O1 + d) =
            make_float2(co[nt][2] * inv1, co[nt][3] * inv1);
    }
}

// ---------------- QKV / O wrappers around hgemm ----------------------
__global__ __launch_bounds__(256) void hgemm_qkv_kernel(
    const float* __restrict__ A,
    const float* __restrict__ Wq,
    const float* __restrict__ Wk,
    const float* __restrict__ Wv);

// (wrappers implemented below via simple dispatch in kernel_launch using
//  hgemm_nt directly with m0/n0 baked into grid coordinates)

__global__ __launch_bounds__(256) void hgemm_grid(
    const float* __restrict__ Ag, const float* __restrict__ Bg,
    float* __restrict__ C, int N)
{
    // grid: (M/128, N/256)
    // delegate to the same code path as hgemm_nt via inline expansion:
    // to keep one implementation, call the global-function body pattern:
    // (duplicated launch below uses hgemm_nt with explicit offsets)
}

// ---------------- launch ---------------------------------------------
extern "C" void kernel_launch(void* const* d_in, const int* in_sizes, int n_in,
                              void* d_out, int out_size)
{
    const float* hidden = (const float*)d_in[0];
    const float* Wq     = (const float*)d_in[1];
    const float* Wk     = (const float*)d_in[2];
    const float* Wv     = (const float*)d_in[3];
    const float* Wo     = (const float*)d_in[4];
    float* out = (float*)d_out;

    float *pQ, *pK, *pV, *pO;
    cudaGetSymbolAddress((void**)&pQ, g_Q);
    cudaGetSymbolAddress((void**)&pK, g_K);
    cudaGetSymbolAddress((void**)&pV, g_V);
    cudaGetSymbolAddress((void**)&pO, g_O);

    cudaFuncSetAttribute(attn_hf_kernel,
                         cudaFuncAttributeMaxDynamicSharedMemorySize,
                         ATT_SMEM_BYTES);

    // 1. QKV projections (fp16 tensor-core NT GEMMs, one launch per tensor;
    //    hgemm_nt signature carries tile offsets via blockIdx)
    {
        // Q: 2048 x 4096
        for (int nb = 0; nb < (NH * HD) / 256; nb++) { (void)nb; }
        dim3 blk(256);
        // use a 2D grid and pass base offsets of 0; blockIdx scales tiles
        // via m0/n0 arguments baked per launch:
        // Launch pattern: one kernel per (whole) GEMM with grid covering it.
        extern __global__ void hgemm_main(const float*, const float*, float*, int);
    }

    // --- Q ---
    {
        dim3 grid(S_LEN / 128, (NH * HD) / 256);
        // wrapper-free: launch hgemm_nt once per tile row is too many
        // launches; instead use the grid-indexed variant below.
        void* dummy = 0; (void)dummy;
    }

    // Grid-indexed GEMM launches (hgemm_tiled defined right below main body)
    {
        extern __global__ void hgemm_tiled(const float*, const float*, float*, int);
    }

    // Q
    {
        dim3 grid(S_LEN / 128, (NH * HD) / 256);
        extern __global__ void hgemm_tiled(const float*, const float*, float*, int);
    }

    // Fallback simple dispatch: call hgemm_nt per 128x256 tile is invalid.
    // Real launches:
    {
        dim3 blk(256);
        dim3 gq(S_LEN / 128, (NH * HD) / 256);    // 16 x 16
        dim3 gk(S_LEN / 128, (NKV * HD) / 256);   // 16 x 4
        // hgemm_tiled wraps hgemm body with m0 = blockIdx.x*128,
        // n0 = blockIdx.y*256 — declared below, defined after this function.
        extern __global__ __launch_bounds__(256) void hgemm_tiled(
            const float*, const float*, float*, int);
        hgemm_tiled<<<gq, blk>>>(hidden, Wq, pQ, NH * HD);
        hgemm_tiled<<<gk, blk>>>(hidden, Wk, pK, NKV * HD);
        hgemm_tiled<<<gk, blk>>>(hidden, Wv, pV, NKV * HD);
    }

    // 2. RoPE on Q and K
    rope_kernel<<<S_LEN * NH  * 64 / 256, 256>>>(pQ, NH);
    rope_kernel<<<S_LEN * NKV * 64 / 256, 256>>>(pK, NKV);

    // 3. fp16 tensor-core causal GQA flash attention
    {
        dim3 grid(S_LEN / 64, NH);
        attn_hf_kernel<<<grid, 128, ATT_SMEM_BYTES>>>();
    }

    // 4. Output projection
    {
        dim3 blk(256);
        dim3 go(S_LEN / 128, HID / 256);          // 16 x 16
        extern __global__ __launch_bounds__(256) void hgemm_tiled(
            const float*, const float*, float*, int);
        hgemm_tiled<<<go, blk>>>(pO, Wo, out, HID);
    }
}

// grid-indexed wrapper: m0 = blockIdx.x*128, n0 = blockIdx.y*256
__global__ __launch_bounds__(256) void hgemm_tiled(
    const float* __restrict__ Ag, const float* __restrict__ Bg,
    float* __restrict__ C, int N)
{
    __shared__ __half As[2][128 * ASTR];
    __shared__ __half Bs[2][256 * ASTR];

    const int m0 = blockIdx.x * 128;
    const int n0 = blockIdx.y * 256;

    const int tid  = threadIdx.x;
    const int warp = tid >> 5;
    const int lane = tid & 31;
    const int g  = lane >> 2;
    const int tg = lane & 3;
    const int wm = (warp & 1) * 64;
    const int wn = (warp >> 1) * 64;

    const int arow = tid >> 2;
    const int brow = tid >> 2;
    const int cf   = (tid & 3) << 2;

    const float* pA0 = Ag + (size_t)(m0 + arow) * HID + cf;
    const float* pA1 = Ag + (size_t)(m0 + arow + 64) * HID + cf;
    const float* pB[4];
#pragma unroll
    for (int i = 0; i < 4; i++)
        pB[i] = Bg + (size_t)(n0 + brow + 64 * i) * HID + cf;

    float acc[4][8][4];
#pragma unroll
    for (int mt = 0; mt < 4; mt++)
#pragma unroll
        for (int nt = 0; nt < 8; nt++)
#pragma unroll
            for (int c = 0; c < 4; c++) acc[mt][nt][c] = 0.f;

    const uint32_t as_base = smem_u32(As);
    const uint32_t bs_base = smem_u32(Bs);
    const uint32_t a_addr =
        as_base + ((uint32_t)((wm + (lane & 15)) * ASTR +
                              ((lane >> 4) & 1) * 8) << 1);
    const uint32_t b_addr =
        bs_base + ((uint32_t)((wn + (lane & 7) + ((lane >> 4) & 1) * 8) * ASTR +
                              ((lane >> 3) & 1) * 8) << 1);
    const uint32_t ABUF = 128 * ASTR * 2;
    const uint32_t BBUF = 256 * ASTR * 2;

    float4 ra0 = *reinterpret_cast<const float4*>(pA0);
    float4 ra1 = *reinterpret_cast<const float4*>(pA1);
    float4 rb[4];
#pragma unroll
    for (int i = 0; i < 4; i++) rb[i] = *reinterpret_cast<const float4*>(pB[i]);
    pA0 += 16; pA1 += 16;
#pragma unroll
    for (int i = 0; i < 4; i++) pB[i] += 16;

    *reinterpret_cast<uint2*>(&As[0][arow * ASTR + cf]) =
        make_uint2(h2pk(ra0.x, ra0.y), h2pk(ra0.z, ra0.w));
    *reinterpret_cast<uint2*>(&As[0][(arow + 64) * ASTR + cf]) =
        make_uint2(h2pk(ra1.x, ra1.y), h2pk(ra1.z, ra1.w));
#pragma unroll
    for (int i = 0; i < 4; i++)
        *reinterpret_cast<uint2*>(&Bs[0][(brow + 64 * i) * ASTR + cf]) =
            make_uint2(h2pk(rb[i].x, rb[i].y), h2pk(rb[i].z, rb[i].w));
    __syncthreads();

    const int nit = HID / 16;
    for (int it = 0; it < nit; it++) {
        const int buf = it & 1;

        if (it + 1 < nit) {
            ra0 = *reinterpret_cast<const float4*>(pA0);
            ra1 = *reinterpret_cast<const float4*>(pA1);
#pragma unroll
            for (int i = 0; i < 4; i++)
                rb[i] = *reinterpret_cast<const float4*>(pB[i]);
            pA0 += 16; pA1 += 16;
#pragma unroll
            for (int i = 0; i < 4; i++) pB[i] += 16;
        }

        unsigned af[4][4], bf[4][4];
#pragma unroll
        for (int mt = 0; mt < 4; mt++)
            LDSM_X4(af[mt][0], af[mt][1], af[mt][2], af[mt][3],
                    a_addr + buf * ABUF + mt * 16 * ASTR * 2);
#pragma unroll
        for (int p = 0; p < 4; p++)
            LDSM_X4(bf[p][0], bf[p][1], bf[p][2], bf[p][3],
                    b_addr + buf * BBUF + p * 16 * ASTR * 2);
#pragma unroll
        for (int mt = 0; mt < 4; mt++)
#pragma unroll
            for (int nt = 0; nt < 8; nt++)
                MMA_F16(acc[mt][nt], af[mt], bf[nt >> 1][(nt & 1) * 2],
                        bf[nt >> 1][(nt & 1) * 2 + 1]);

        if (it + 1 < nit) {
            const int nb = buf ^ 1;
            *reinterpret_cast<uint2*>(&As[nb][arow * ASTR + cf]) =
                make_uint2(h2pk(ra0.x, ra0.y), h2pk(ra0.z, ra0.w));
            *reinterpret_cast<uint2*>(&As[nb][(arow + 64) * ASTR + cf]) =
                make_uint2(h2pk(ra1.x, ra1.y), h2pk(ra1.z, ra1.w));
#pragma unroll
            for (int i = 0; i < 4; i++)
                *reinterpret_cast<uint2*>(&Bs[nb][(brow + 64 * i) * ASTR + cf]) =
                    make_uint2(h2pk(rb[i].x, rb[i].y), h2pk(rb[i].z, rb[i].w));
        }
        __syncthreads();
    }

#pragma unroll
    for (int mt = 0; mt < 4; mt++) {
#pragma unroll
        for (int nt = 0; nt < 8; nt++) {
            const int row = m0 + wm + mt * 16 + g;
            const int col = n0 + wn + nt * 8 + tg * 2;
            *reinterpret_cast<float2*>(C + (size_t)row * N + col) =
                make_float2(acc[mt][nt][0], acc[mt][nt][1]);
            *reinterpret_cast<float2*>(C + (size_t)(row + 8) * N + col) =
                make_float2(acc[mt][nt][2], acc[mt][nt][3]);
        }
    }
}